// round 7
// baseline (speedup 1.0000x reference)
#include <cuda_runtime.h>
#include <cuda_bf16.h>
#include <cstdint>
#include <math.h>

#define SEQ 3072
#define DIM 1024
#define NHEAD 4
#define DHEAD 256
#define NLAYER 4
#define LN_EPS 1e-5f
typedef __nv_bfloat16 bf16;

// ======================= scratch (static device arrays) =======================
__device__ float g_h[SEQ * DIM];
__device__ float g_tmp[SEQ * DIM];

__device__ bf16 g_h_hi[SEQ * DIM],   g_h_lo[SEQ * DIM];
__device__ bf16 g_qkv_hi[3 * SEQ * DIM],  g_qkv_lo[3 * SEQ * DIM];   // [qkv][t][d]
__device__ bf16 g_qkvh_hi[3 * SEQ * DIM], g_qkvh_lo[3 * SEQ * DIM];  // [qkv][head][t][e]
__device__ bf16 g_vht_hi[SEQ * DIM], g_vht_lo[SEQ * DIM];            // [head][e][t]
__device__ bf16 g_ctx_hi[SEQ * DIM], g_ctx_lo[SEQ * DIM];            // [t][head*DHEAD+e]
__device__ bf16 g_f1_hi[SEQ * 2 * DIM], g_f1_lo[SEQ * 2 * DIM];
__device__ bf16 g_at_hi[(size_t)NHEAD * SEQ * SEQ];                  // scores/attn hi
__device__ bf16 g_at_lo[(size_t)NHEAD * SEQ * SEQ];                  // scores/attn lo

// transposed weights [N][K] bf16 hi/lo
__device__ bf16 g_wqkv_hi[NLAYER * 3 * DIM * DIM], g_wqkv_lo[NLAYER * 3 * DIM * DIM];
__device__ bf16 g_wot_hi[NLAYER * DIM * DIM],  g_wot_lo[NLAYER * DIM * DIM];
__device__ bf16 g_wht_hi[NLAYER * NHEAD * DIM * DHEAD], g_wht_lo[NLAYER * NHEAD * DIM * DHEAD];
__device__ bf16 g_w1t_hi[NLAYER * DIM * 2 * DIM], g_w1t_lo[NLAYER * DIM * 2 * DIM];
__device__ bf16 g_w2t_hi[NLAYER * 2 * DIM * DIM], g_w2t_lo[NLAYER * 2 * DIM * DIM];
__device__ float g_bqkv[NLAYER * 3 * DIM];

// ======================= helpers =======================
__device__ __forceinline__ uint32_t s2u(const void* p) {
    uint32_t a;
    asm("{ .reg .u64 t; cvta.to.shared.u64 t, %1; cvt.u32.u64 %0, t; }" : "=r"(a) : "l"(p));
    return a;
}
__device__ __forceinline__ void split2(float x, bf16& h, bf16& l) {
    h = __float2bfloat16(x);
    l = __float2bfloat16(x - __bfloat162float(h));
}
__device__ __forceinline__ void cp16(uint32_t dst, const void* src) {
    asm volatile("cp.async.cg.shared.global [%0], [%1], 16;" :: "r"(dst), "l"(src) : "memory");
}
#define CP_COMMIT() asm volatile("cp.async.commit_group;" ::: "memory")
#define CP_WAIT(n)  asm volatile("cp.async.wait_group %0;" :: "n"(n) : "memory")

__device__ __forceinline__ void ldm_x4(uint32_t* r, uint32_t addr) {
    asm volatile("ldmatrix.sync.aligned.m8n8.x4.shared.b16 {%0,%1,%2,%3}, [%4];"
                 : "=r"(r[0]), "=r"(r[1]), "=r"(r[2]), "=r"(r[3]) : "r"(addr));
}
__device__ __forceinline__ void mma_bf16(float* c, const uint32_t* a, const uint32_t* b) {
    asm volatile(
        "mma.sync.aligned.m16n8k16.row.col.f32.bf16.bf16.f32 "
        "{%0,%1,%2,%3}, {%4,%5,%6,%7}, {%8,%9}, {%0,%1,%2,%3};"
        : "+f"(c[0]), "+f"(c[1]), "+f"(c[2]), "+f"(c[3])
        : "r"(a[0]), "r"(a[1]), "r"(a[2]), "r"(a[3]), "r"(b[0]), "r"(b[1]));
}

// ======================= split-bf16 mma.sync GEMM =======================
// C[m][n] = alpha * sum_k A[m][k]*B[n][k] + bias[n]   (A,B as hi/lo bf16)
// CTA tile 128x256, 8 warps of 64x64, BK=32, 3-stage cp.async, SW64 swizzle.
// Per stage (48KB): Ahi 8K | Alo 8K | Bhi 16K | Blo 16K. Requires N%256==0.
// Batch decomposition: z -> (zo = z/nB, zi = z%nB);
//   A offset = zo*sAo + zi*sAi, B/bias offset = zo*sBo + zi*sBi, C offset = z*sC.
#define GSMEM_BYTES 147456
#define STAGE_BYTES 49152u

__global__ void __launch_bounds__(256, 1)
mma_gemm(const bf16* __restrict__ Ahi, const bf16* __restrict__ Alo, int lda, long sAo, long sAi,
         const bf16* __restrict__ Bhi, const bf16* __restrict__ Blo, int ldb, long sBo, long sBi,
         const float* __restrict__ bias, long sBias, int nB,
         float* __restrict__ C, bf16* __restrict__ Chi, bf16* __restrict__ Clo,
         int ldc, long sC, int K, float alpha, int relu)
{
    extern __shared__ char sm[];
    const uint32_t sb = s2u(sm);
    const int tid = threadIdx.x;
    const int wid = tid >> 5;
    const int lane = tid & 31;
    const int wm = wid >> 2;        // 0..1  (M, 64 rows each)
    const int wn = wid & 3;         // 0..3  (N, 64 cols each)
    const int z = blockIdx.z;
    const int zo = z / nB;
    const int zi = z - zo * nB;
    const long row0 = (long)blockIdx.y * 128;
    const long col0 = (long)blockIdx.x * 256;

    Ahi += zo * sAo + zi * sAi; Alo += zo * sAo + zi * sAi;
    Bhi += zo * sBo + zi * sBi; Blo += zo * sBo + zi * sBi;

    const int nch = K >> 5;

    // ---- async load of one 32-k chunk (48KB) : 12 x 16B per thread ----
    auto load_chunk = [&](int ch, int stage) {
        const long k0 = (long)ch << 5;
        const uint32_t sbase = sb + (uint32_t)stage * STAGE_BYTES;
#pragma unroll
        for (int i = 0; i < 12; i++) {
            const int u = tid + (i << 8);
            const bf16* p;
            uint32_t dst;
            if (u < 1024) {                       // A tiles: 128 rows x 64B, hi|lo
                const int t = u >> 9;             // 0=hi 1=lo
                const int q = u & 511;
                const long r = q >> 2;
                const int sg = (q & 3) << 3;
                p = (t ? Alo : Ahi) + (row0 + r) * lda + k0 + sg;
                uint32_t off = (uint32_t)(q << 4);
                off ^= (off >> 3) & 0x30;
                dst = sbase + (uint32_t)t * 8192u + off;
            } else {                              // B tiles: 256 rows x 64B, hi|lo
                const int u2 = u - 1024;
                const int t = u2 >> 10;           // 0=hi 1=lo
                const int q = u2 & 1023;
                const long r = q >> 2;
                const int sg = (q & 3) << 3;
                p = (t ? Blo : Bhi) + (col0 + r) * ldb + k0 + sg;
                uint32_t off = (uint32_t)(q << 4);
                off ^= (off >> 3) & 0x30;
                dst = sbase + 16384u + (uint32_t)t * 16384u + off;
            }
            cp16(dst, p);
        }
        CP_COMMIT();
    };

    float acc[4][8][4];
#pragma unroll
    for (int a = 0; a < 4; a++)
#pragma unroll
        for (int b = 0; b < 8; b++)
#pragma unroll
            for (int c = 0; c < 4; c++) acc[a][b][c] = 0.0f;

    load_chunk(0, 0);
    load_chunk(1, 1);

    for (int ch = 0; ch < nch; ch++) {
        if (ch + 2 < nch) {
            load_chunk(ch + 2, (ch + 2) % 3);
            CP_WAIT(2);
        } else {
            CP_WAIT(0);
        }
        __syncthreads();

        const uint32_t stg = sb + (uint32_t)(ch % 3) * STAGE_BYTES;

#pragma unroll
        for (int ks = 0; ks < 2; ks++) {
            uint32_t ah[4][4], al[4][4], bh[4][4], bl[4][4];
#pragma unroll
            for (int mt = 0; mt < 4; mt++) {
                const int row = wm * 64 + mt * 16 + (lane & 15);
                const int colb = ks * 32 + ((lane >> 4) << 4);
                uint32_t off = (uint32_t)(row * 64 + colb);
                off ^= (off >> 3) & 0x30;
                ldm_x4(ah[mt], stg + off);
                ldm_x4(al[mt], stg + 8192u + off);
            }
#pragma unroll
            for (int nb = 0; nb < 4; nb++) {
                const int row = wn * 64 + nb * 16 + (lane & 7) + ((lane >> 4) << 3);
                const int colb = ks * 32 + (((lane >> 3) & 1) << 4);
                uint32_t off = (uint32_t)(row * 64 + colb);
                off ^= (off >> 3) & 0x30;
                ldm_x4(bh[nb], stg + 16384u + off);
                ldm_x4(bl[nb], stg + 32768u + off);
            }
#pragma unroll
            for (int mt = 0; mt < 4; mt++)
#pragma unroll
                for (int nt = 0; nt < 8; nt++) {
                    const uint32_t* bhp = &bh[nt >> 1][(nt & 1) * 2];
                    const uint32_t* blp = &bl[nt >> 1][(nt & 1) * 2];
                    mma_bf16(acc[mt][nt], ah[mt], bhp);
                    mma_bf16(acc[mt][nt], ah[mt], blp);
                    mma_bf16(acc[mt][nt], al[mt], bhp);
                }
        }
        __syncthreads();
    }

    // -------- epilogue --------
    float* Cz = C ? C + sC * z : nullptr;
    bf16* Hz = Chi ? Chi + sC * z : nullptr;
    bf16* Lz = Clo ? Clo + sC * z : nullptr;
    const float* bz = bias ? bias + (long)zi * sBias : nullptr;

#pragma unroll
    for (int mt = 0; mt < 4; mt++)
#pragma unroll
        for (int nt = 0; nt < 8; nt++) {
            float* d = acc[mt][nt];
            const long gm = row0 + wm * 64 + mt * 16 + (lane >> 2);
            const long gn = col0 + wn * 64 + nt * 8 + (lane & 3) * 2;
            float b0 = 0.0f, b1 = 0.0f;
            if (bz) { b0 = __ldg(bz + gn); b1 = __ldg(bz + gn + 1); }
#pragma unroll
            for (int half = 0; half < 2; half++) {
                const long r = gm + half * 8;
                float x0 = d[half * 2 + 0] * alpha + b0;
                float x1 = d[half * 2 + 1] * alpha + b1;
                if (relu) { x0 = fmaxf(x0, 0.0f); x1 = fmaxf(x1, 0.0f); }
                const long o = r * ldc + gn;
                if (Cz) *(float2*)(Cz + o) = make_float2(x0, x1);
                if (Hz) {
                    bf16 h0, l0, h1, l1;
                    split2(x0, h0, l0); split2(x1, h1, l1);
                    uint32_t wh = (uint32_t)__bfloat16_as_ushort(h0) |
                                  ((uint32_t)__bfloat16_as_ushort(h1) << 16);
                    uint32_t wl = (uint32_t)__bfloat16_as_ushort(l0) |
                                  ((uint32_t)__bfloat16_as_ushort(l1) << 16);
                    *(uint32_t*)(Hz + o) = wh;
                    *(uint32_t*)(Lz + o) = wl;
                }
            }
        }
}

// ======================= transpose + split: [R][C] f32 -> [C][R] bf16 hi/lo ====
__global__ void __launch_bounds__(256)
transpose_split(const float* __restrict__ in, bf16* __restrict__ ohi, bf16* __restrict__ olo,
                int R, int Ccols, long sIn, long sOut)
{
    __shared__ float t[32][33];
    const float* ip = in + sIn * blockIdx.z;
    const int c0 = blockIdx.x * 32, r0 = blockIdx.y * 32;
    const int tx = threadIdx.x & 31, ty = threadIdx.x >> 5;
#pragma unroll
    for (int j = 0; j < 32; j += 8)
        t[ty + j][tx] = ip[(long)(r0 + ty + j) * Ccols + c0 + tx];
    __syncthreads();
#pragma unroll
    for (int j = 0; j < 32; j += 8) {
        float x = t[tx][ty + j];
        bf16 h, l; split2(x, h, l);
        long o = sOut * blockIdx.z + (long)(c0 + ty + j) * R + r0 + tx;
        ohi[o] = h; olo[o] = l;
    }
}

// ======= combined transpose for Wq/Wk/Wv/Wo (all DIMxDIM, NLAYER each) =========
__global__ void __launch_bounds__(256)
transpose_wqkvo(const float* __restrict__ Wq, const float* __restrict__ Wk,
                const float* __restrict__ Wv, const float* __restrict__ Wo,
                bf16* __restrict__ wqkv_hi, bf16* __restrict__ wqkv_lo,
                bf16* __restrict__ wot_hi, bf16* __restrict__ wot_lo)
{
    __shared__ float t[32][33];
    const long DD = (long)DIM * DIM;
    const int w = blockIdx.z / NLAYER;
    const int l = blockIdx.z - w * NLAYER;
    const float* ip = ((w == 0) ? Wq : (w == 1) ? Wk : (w == 2) ? Wv : Wo) + l * DD;
    bf16* ohi; bf16* olo;
    if (w < 3) { ohi = wqkv_hi + l * 3 * DD + w * DD; olo = wqkv_lo + l * 3 * DD + w * DD; }
    else       { ohi = wot_hi + l * DD;               olo = wot_lo + l * DD; }
    const int c0 = blockIdx.x * 32, r0 = blockIdx.y * 32;
    const int tx = threadIdx.x & 31, ty = threadIdx.x >> 5;
#pragma unroll
    for (int j = 0; j < 32; j += 8)
        t[ty + j][tx] = ip[(long)(r0 + ty + j) * DIM + c0 + tx];
    __syncthreads();
#pragma unroll
    for (int j = 0; j < 32; j += 8) {
        float x = t[tx][ty + j];
        bf16 h, l2; split2(x, h, l2);
        long o = (long)(c0 + ty + j) * DIM + r0 + tx;
        ohi[o] = h; olo[o] = l2;
    }
}

// ======================= bf16 hi/lo pair transpose: [R][C] -> [C][R] ============
__global__ void __launch_bounds__(256)
transpose_pair(const bf16* __restrict__ ihi, const bf16* __restrict__ ilo,
               bf16* __restrict__ ohi, bf16* __restrict__ olo,
               int R, int Ccols, long sIn, long sOut)
{
    __shared__ unsigned short t[32][33];
    const int c0 = blockIdx.x * 32, r0 = blockIdx.y * 32;
    const int tx = threadIdx.x & 31, ty = threadIdx.x >> 5;
    const bf16* a = ihi + sIn * blockIdx.z;
    bf16* o = ohi + sOut * blockIdx.z;
#pragma unroll
    for (int pass = 0; pass < 2; pass++) {
#pragma unroll
        for (int j = 0; j < 32; j += 8)
            t[ty + j][tx] = __bfloat16_as_ushort(a[(long)(r0 + ty + j) * Ccols + c0 + tx]);
        __syncthreads();
#pragma unroll
        for (int j = 0; j < 32; j += 8)
            o[(long)(c0 + ty + j) * R + r0 + tx] = __ushort_as_bfloat16(t[tx][ty + j]);
        __syncthreads();
        a = ilo + sIn * blockIdx.z;
        o = olo + sOut * blockIdx.z;
    }
}

// ======== fused prologue misc: copy_split(hidden) + concat_bias =================
__global__ void __launch_bounds__(256)
prep_misc(const float* __restrict__ hidden, float* __restrict__ h,
          bf16* __restrict__ dhi, bf16* __restrict__ dlo,
          const float* __restrict__ bq, const float* __restrict__ bk,
          const float* __restrict__ bv, float* __restrict__ bqkv)
{
    const int n1 = SEQ * DIM;
    const int idx = blockIdx.x * blockDim.x + threadIdx.x;
    if (idx < n1) {
        float v = hidden[idx];
        h[idx] = v;
        bf16 hh, ll; split2(v, hh, ll);
        dhi[idx] = hh; dlo[idx] = ll;
    } else {
        const int j = idx - n1;
        if (j < NLAYER * 3 * DIM) {
            const int l = j / (3 * DIM);
            const int w = (j / DIM) % 3;
            const int i = j % DIM;
            const float* src = (w == 0) ? bq : (w == 1) ? bk : bv;
            bqkv[j] = src[l * DIM + i];
        }
    }
}

// ============ softmax over rows (bf16 hi/lo in, in-place hi/lo out) ============
__global__ void __launch_bounds__(256)
softmax_kernel(bf16* __restrict__ shi, bf16* __restrict__ slo)
{
    const size_t base = (size_t)blockIdx.x * SEQ;
    const int tid = threadIdx.x;

    float v[12];
    float mx = -1e30f;
#pragma unroll
    for (int i = 0; i < 12; i++) {
        const size_t o = base + tid + i * 256;
        v[i] = __bfloat162float(shi[o]) + __bfloat162float(slo[o]);
        mx = fmaxf(mx, v[i]);
    }
    __shared__ float red[256];
    red[tid] = mx;
    __syncthreads();
    for (int s = 128; s > 0; s >>= 1) {
        if (tid < s) red[tid] = fmaxf(red[tid], red[tid + s]);
        __syncthreads();
    }
    mx = red[0];
    __syncthreads();

    float sum = 0.0f;
#pragma unroll
    for (int i = 0; i < 12; i++) {
        v[i] = __expf(v[i] - mx);
        sum += v[i];
    }
    red[tid] = sum;
    __syncthreads();
    for (int s = 128; s > 0; s >>= 1) {
        if (tid < s) red[tid] += red[tid + s];
        __syncthreads();
    }
    const float inv = 1.0f / red[0];
#pragma unroll
    for (int i = 0; i < 12; i++) {
        float x = v[i] * inv;
        bf16 h, l; split2(x, h, l);
        const size_t o = base + tid + i * 256;
        shi[o] = h;
        slo[o] = l;
    }
}

// ======================= add + layernorm (emit f32 + hi/lo) ====================
__global__ void __launch_bounds__(256)
add_ln_kernel(float* __restrict__ h, const float* __restrict__ x,
              const float* __restrict__ g, const float* __restrict__ b,
              bf16* __restrict__ ohi, bf16* __restrict__ olo)
{
    const long row = blockIdx.x;
    float* hp = h + row * (long)DIM;
    const float* xp = x + row * (long)DIM;
    const int tid = threadIdx.x;

    float v[4];
    float sum = 0.0f;
#pragma unroll
    for (int i = 0; i < 4; i++) {
        const int c = tid + i * 256;
        v[i] = hp[c] + xp[c];
        sum += v[i];
    }
    __shared__ float red[256];
    red[tid] = sum;
    __syncthreads();
    for (int s = 128; s > 0; s >>= 1) {
        if (tid < s) red[tid] += red[tid + s];
        __syncthreads();
    }
    const float mu = red[0] * (1.0f / DIM);
    __syncthreads();

    float vs = 0.0f;
#pragma unroll
    for (int i = 0; i < 4; i++) {
        const float d = v[i] - mu;
        vs += d * d;
    }
    red[tid] = vs;
    __syncthreads();
    for (int s = 128; s > 0; s >>= 1) {
        if (tid < s) red[tid] += red[tid + s];
        __syncthreads();
    }
    const float inv = rsqrtf(red[0] * (1.0f / DIM) + LN_EPS);
    __syncthreads();
#pragma unroll
    for (int i = 0; i < 4; i++) {
        const int c = tid + i * 256;
        float y = g[c] * (v[i] - mu) * inv + b[c];
        hp[c] = y;
        bf16 hh, ll; split2(y, hh, ll);
        ohi[row * (long)DIM + c] = hh;
        olo[row * (long)DIM + c] = ll;
    }
}

// ======================= output heads =======================
__global__ void __launch_bounds__(256)
heads_kernel(const float* __restrict__ h, const float* __restrict__ Whead,
             const float* __restrict__ bhead, const int* __restrict__ nev,
             const int* __restrict__ nag, float* __restrict__ out, int total)
{
    const int warpId = (blockIdx.x * blockDim.x + threadIdx.x) >> 5;
    const int lane = threadIdx.x & 31;
    if (warpId >= total) return;
    const int NEv = *nev;
    const int NAg = *nag;
    int headIdx, token;
    if (warpId < 3 * NAg) {
        headIdx = warpId / NAg;
        token = NEv + warpId % NAg;
    } else {
        headIdx = 3;
        token = warpId - 3 * NAg;
    }
    const float* hr = h + (long)token * DIM;
    const float* w = Whead + (long)headIdx * DIM;
    float s = 0.0f;
    for (int i = lane; i < DIM; i += 32) s = fmaf(hr[i], w[i], s);
#pragma unroll
    for (int off = 16; off > 0; off >>= 1) s += __shfl_down_sync(0xFFFFFFFFu, s, off);
    if (lane == 0) out[warpId] = s + bhead[headIdx];
}

// ======================= host orchestration =======================
static void tcg(const bf16* Ahi, const bf16* Alo, int lda, long sAo, long sAi,
                const bf16* Bhi, const bf16* Blo, int ldb, long sBo, long sBi,
                const float* bias, long sBias, int nB,
                float* C, bf16* Chi, bf16* Clo, int ldc, long sC,
                int M, int N, int K, int batch, float alpha, int relu)
{
    dim3 grid(N / 256, M / 128, batch);
    mma_gemm<<<grid, 256, GSMEM_BYTES>>>(Ahi, Alo, lda, sAo, sAi, Bhi, Blo, ldb, sBo, sBi,
                                         bias, sBias, nB, C, Chi, Clo, ldc, sC, K, alpha, relu);
}

#define SYM(var, name) cudaGetSymbolAddress((void**)&var, name)

extern "C" void kernel_launch(void* const* d_in, const int* in_sizes, int n_in,
                              void* d_out, int out_size)
{
    const float* hidden = (const float*)d_in[0];
    const float* Wq = (const float*)d_in[1];
    const float* bq = (const float*)d_in[2];
    const float* Wk = (const float*)d_in[3];
    const float* bk = (const float*)d_in[4];
    const float* Wv = (const float*)d_in[5];
    const float* bv = (const float*)d_in[6];
    const float* Wh = (const float*)d_in[7];
    const float* bh = (const float*)d_in[8];
    const float* Wo = (const float*)d_in[9];
    const float* bo = (const float*)d_in[10];
    const float* g1 = (const float*)d_in[11];
    const float* b1n = (const float*)d_in[12];
    const float* g2 = (const float*)d_in[13];
    const float* b2n = (const float*)d_in[14];
    const float* Wf1 = (const float*)d_in[15];
    const float* bf1 = (const float*)d_in[16];
    const float* Wf2 = (const float*)d_in[17];
    const float* bf2 = (const float*)d_in[18];
    const float* Whead = (const float*)d_in[19];
    const float* bhead = (const float*)d_in[20];
    const int* n_events = (const int*)d_in[21];
    const int* n_agents = (const int*)d_in[22];
    (void)in_sizes; (void)n_in;

    cudaFuncSetAttribute(mma_gemm, cudaFuncAttributeMaxDynamicSharedMemorySize, GSMEM_BYTES);

    float *h, *tmp, *bqkv;
    SYM(h, g_h); SYM(tmp, g_tmp); SYM(bqkv, g_bqkv);
    bf16 *h_hi, *h_lo, *qkv_hi, *qkv_lo, *qkvh_hi, *qkvh_lo;
    bf16 *vht_hi, *vht_lo, *ctx_hi, *ctx_lo, *f1_hi, *f1_lo, *at_hi, *at_lo;
    SYM(h_hi, g_h_hi); SYM(h_lo, g_h_lo);
    SYM(qkv_hi, g_qkv_hi); SYM(qkv_lo, g_qkv_lo);
    SYM(qkvh_hi, g_qkvh_hi); SYM(qkvh_lo, g_qkvh_lo);
    SYM(vht_hi, g_vht_hi); SYM(vht_lo, g_vht_lo);
    SYM(ctx_hi, g_ctx_hi); SYM(ctx_lo, g_ctx_lo);
    SYM(f1_hi, g_f1_hi); SYM(f1_lo, g_f1_lo);
    SYM(at_hi, g_at_hi); SYM(at_lo, g_at_lo);
    bf16 *wqkv_hi, *wqkv_lo, *wot_hi, *wot_lo, *wht_hi, *wht_lo;
    bf16 *w1t_hi, *w1t_lo, *w2t_hi, *w2t_lo;
    SYM(wqkv_hi, g_wqkv_hi); SYM(wqkv_lo, g_wqkv_lo);
    SYM(wot_hi, g_wot_hi); SYM(wot_lo, g_wot_lo);
    SYM(wht_hi, g_wht_hi); SYM(wht_lo, g_wht_lo);
    SYM(w1t_hi, g_w1t_hi); SYM(w1t_lo, g_w1t_lo);
    SYM(w2t_hi, g_w2t_hi); SYM(w2t_lo, g_w2t_lo);

    const long DD = (long)DIM * DIM;
    const long SD = (long)SEQ * DIM;
    const long SS = (long)SEQ * SEQ;
    const long SDh = (long)SEQ * DHEAD;
    const long WHL = (long)NHEAD * DIM * DHEAD;

    // ---- prologue: 5 launches ----
    transpose_wqkvo<<<dim3(DIM / 32, DIM / 32, 4 * NLAYER), 256>>>(
        Wq, Wk, Wv, Wo, wqkv_hi, wqkv_lo, wot_hi, wot_lo);
    transpose_split<<<dim3(DHEAD / 32, DIM / 32, NLAYER * NHEAD), 256>>>(
        Wh, wht_hi, wht_lo, DIM, DHEAD, (long)DIM * DHEAD, (long)DIM * DHEAD);
    transpose_split<<<dim3(2 * DIM / 32, DIM / 32, NLAYER), 256>>>(Wf1, w1t_hi, w1t_lo, DIM, 2 * DIM, 2 * DD, 2 * DD);
    transpose_split<<<dim3(DIM / 32, 2 * DIM / 32, NLAYER), 256>>>(Wf2, w2t_hi, w2t_lo, 2 * DIM, DIM, 2 * DD, 2 * DD);
    {
        const int total = SEQ * DIM + NLAYER * 3 * DIM;
        prep_misc<<<(total + 255) / 256, 256>>>(hidden, h, h_hi, h_lo, bq, bk, bv, bqkv);
    }

    const float attn_scale = 1.0f / 16.0f;

    for (int l = 0; l < NLAYER; l++) {
        // QKV projections, one launch (z: 0=Q 1=K 2=V)
        tcg(h_hi, h_lo, DIM, 0, 0,
            wqkv_hi + l * 3 * DD, wqkv_lo + l * 3 * DD, DIM, 0, DD,
            bqkv + (long)l * 3 * DIM, DIM, 3,
            nullptr, qkv_hi, qkv_lo, DIM, SD, SEQ, DIM, DIM, 3, 1.0f, 0);
        // per-head projections, one launch (z = which*4 + head)
        tcg(qkv_hi, qkv_lo, DIM, SD, 0,
            wht_hi + l * WHL, wht_lo + l * WHL, DIM, 0, (long)DIM * DHEAD,
            bh + (long)l * NHEAD * DHEAD, DHEAD, NHEAD,
            nullptr, qkvh_hi, qkvh_lo, DHEAD, SDh, SEQ, DHEAD, DIM, 3 * NHEAD, 1.0f, 0);
        // Vh [head][t][e] -> [head][e][t] (hi and lo transposed independently)
        transpose_pair<<<dim3(DHEAD / 32, SEQ / 32, NHEAD), 256>>>(
            qkvh_hi + 2 * SD, qkvh_lo + 2 * SD, vht_hi, vht_lo, SEQ, DHEAD, SDh, SDh);
        // scores = scale * Qh @ Kh^T  -> hi/lo bf16 directly
        tcg(qkvh_hi, qkvh_lo, DHEAD, SDh, 0,
            qkvh_hi + SD, qkvh_lo + SD, DHEAD, SDh, 0,
            nullptr, 0, 1,
            nullptr, at_hi, at_lo, SEQ, SS, SEQ, SEQ, DHEAD, NHEAD, attn_scale, 0);
        // softmax in-place on hi/lo
        softmax_kernel<<<NHEAD * SEQ, 256>>>(at_hi, at_lo);
        // ctx = attn @ Vh -> [t][head*DHEAD+e]
        tcg(at_hi, at_lo, SEQ, SS, 0,
            vht_hi, vht_lo, SEQ, SDh, 0,
            nullptr, 0, 1,
            nullptr, ctx_hi, ctx_lo, DIM, DHEAD, SEQ, DHEAD, SEQ, NHEAD, 1.0f, 0);
        // attn_out = ctx @ Wo + bo -> f32 tmp
        tcg(ctx_hi, ctx_lo, DIM, 0, 0,
            wot_hi + l * DD, wot_lo + l * DD, DIM, 0, 0,
            bo + (long)l * DIM, 0, 1,
            tmp, nullptr, nullptr, DIM, 0, SEQ, DIM, DIM, 1, 1.0f, 0);
        add_ln_kernel<<<SEQ, 256>>>(h, tmp, g1 + (long)l * DIM, b1n + (long)l * DIM, h_hi, h_lo);
        // FFN
        tcg(h_hi, h_lo, DIM, 0, 0,
            w1t_hi + l * 2 * DD, w1t_lo + l * 2 * DD, DIM, 0, 0,
            bf1 + (long)l * 2 * DIM, 0, 1,
            nullptr, f1_hi, f1_lo, 2 * DIM, 0, SEQ, 2 * DIM, DIM, 1, 1.0f, 1);
        tcg(f1_hi, f1_lo, 2 * DIM, 0, 0,
            w2t_hi + l * 2 * DD, w2t_lo + l * 2 * DD, 2 * DIM, 0, 0,
            bf2 + (long)l * DIM, 0, 1,
            tmp, nullptr, nullptr, DIM, 0, SEQ, DIM, 2 * DIM, 1, 1.0f, 0);
        add_ln_kernel<<<SEQ, 256>>>(h, tmp, g2 + (long)l * DIM, b2n + (long)l * DIM, h_hi, h_lo);
    }

    const int blocks = (out_size * 32 + 255) / 256;
    heads_kernel<<<blocks, 256>>>(h, Whead, bhead, n_events, n_agents, (float*)d_out, out_size);
}

// round 8
// speedup vs baseline: 1.1377x; 1.1377x over previous
#include <cuda_runtime.h>
#include <cuda_bf16.h>
#include <cstdint>
#include <math.h>

#define SEQ 3072
#define DIM 1024
#define NHEAD 4
#define DHEAD 256
#define NLAYER 4
#define LN_EPS 1e-5f
typedef __nv_bfloat16 bf16;

// ======================= scratch (static device arrays) =======================
__device__ float g_h[SEQ * DIM];
__device__ float g_tmp[SEQ * DIM];

__device__ bf16 g_h_hi[SEQ * DIM],   g_h_lo[SEQ * DIM];
__device__ bf16 g_qkvh_hi[3 * SEQ * DIM], g_qkvh_lo[3 * SEQ * DIM];  // [qkv][head][t][e]
__device__ bf16 g_vht_hi[SEQ * DIM], g_vht_lo[SEQ * DIM];            // [head][e][t]
__device__ bf16 g_ctx_hi[SEQ * DIM], g_ctx_lo[SEQ * DIM];            // [t][head*DHEAD+e]
__device__ bf16 g_f1_hi[SEQ * 2 * DIM], g_f1_lo[SEQ * 2 * DIM];
__device__ bf16 g_at_hi[(size_t)NHEAD * SEQ * SEQ];                  // scores/attn hi
__device__ bf16 g_at_lo[(size_t)NHEAD * SEQ * SEQ];                  // scores/attn lo

// weights
__device__ bf16 g_wsplit_hi[3 * NLAYER * DIM * DIM], g_wsplit_lo[3 * NLAYER * DIM * DIM]; // [qkv][l][in][out] (plain)
__device__ bf16 g_wpt_hi[3 * NLAYER * NHEAD * DHEAD * DIM];  // W'^T [qkv][l][a][e][in]
__device__ bf16 g_wpt_lo[3 * NLAYER * NHEAD * DHEAD * DIM];
__device__ bf16 g_wot_hi[NLAYER * DIM * DIM],  g_wot_lo[NLAYER * DIM * DIM];
__device__ bf16 g_wht_hi[NLAYER * NHEAD * DHEAD * DIM], g_wht_lo[NLAYER * NHEAD * DHEAD * DIM]; // [l][a][e][in]
__device__ bf16 g_w1t_hi[NLAYER * DIM * 2 * DIM], g_w1t_lo[NLAYER * DIM * 2 * DIM];
__device__ bf16 g_w2t_hi[NLAYER * 2 * DIM * DIM], g_w2t_lo[NLAYER * 2 * DIM * DIM];
__device__ float g_bprime[NLAYER * 3 * NHEAD * DHEAD];       // [l][qkv][a][e]

// ======================= helpers =======================
__device__ __forceinline__ uint32_t s2u(const void* p) {
    uint32_t a;
    asm("{ .reg .u64 t; cvta.to.shared.u64 t, %1; cvt.u32.u64 %0, t; }" : "=r"(a) : "l"(p));
    return a;
}
__device__ __forceinline__ void split2(float x, bf16& h, bf16& l) {
    h = __float2bfloat16(x);
    l = __float2bfloat16(x - __bfloat162float(h));
}
__device__ __forceinline__ void cp16(uint32_t dst, const void* src) {
    asm volatile("cp.async.cg.shared.global [%0], [%1], 16;" :: "r"(dst), "l"(src) : "memory");
}
#define CP_COMMIT() asm volatile("cp.async.commit_group;" ::: "memory")
#define CP_WAIT(n)  asm volatile("cp.async.wait_group %0;" :: "n"(n) : "memory")

__device__ __forceinline__ void ldm_x4(uint32_t* r, uint32_t addr) {
    asm volatile("ldmatrix.sync.aligned.m8n8.x4.shared.b16 {%0,%1,%2,%3}, [%4];"
                 : "=r"(r[0]), "=r"(r[1]), "=r"(r[2]), "=r"(r[3]) : "r"(addr));
}
__device__ __forceinline__ void mma_bf16(float* c, const uint32_t* a, const uint32_t* b) {
    asm volatile(
        "mma.sync.aligned.m16n8k16.row.col.f32.bf16.bf16.f32 "
        "{%0,%1,%2,%3}, {%4,%5,%6,%7}, {%8,%9}, {%0,%1,%2,%3};"
        : "+f"(c[0]), "+f"(c[1]), "+f"(c[2]), "+f"(c[3])
        : "r"(a[0]), "r"(a[1]), "r"(a[2]), "r"(a[3]), "r"(b[0]), "r"(b[1]));
}

// ======================= split-bf16 mma.sync GEMM (R5 winner config) ==========
// C[m][n] = alpha * sum_k A[m][k]*B[n][k] + bias[n]   (A,B as hi/lo bf16)
// Tile 128x128, BK=64 bf16, 3-stage cp.async pipeline, SW128 swizzle, occ 1.
// Batch decomposition: z -> (zo = z/nB, zi = z%nB);
//   A offset = zo*sAo + zi*sAi, B offset = zo*sBo + zi*sBi,
//   bias offset = z*sBias, C offset = z*sC.
#define GSMEM_BYTES 196608

__global__ void __launch_bounds__(256, 1)
mma_gemm(const bf16* __restrict__ Ahi, const bf16* __restrict__ Alo, int lda, long sAo, long sAi,
         const bf16* __restrict__ Bhi, const bf16* __restrict__ Blo, int ldb, long sBo, long sBi,
         const float* __restrict__ bias, long sBias, int nB,
         float* __restrict__ C, bf16* __restrict__ Chi, bf16* __restrict__ Clo,
         int ldc, long sC, int K, float alpha, int relu)
{
    extern __shared__ char sm[];
    const uint32_t sb = s2u(sm);
    const int tid = threadIdx.x;
    const int wid = tid >> 5;
    const int lane = tid & 31;
    const int wm = wid >> 2;        // 0..1  (M)
    const int wn = wid & 3;         // 0..3  (N)
    const int z = blockIdx.z;
    const int zo = z / nB;
    const int zi = z - zo * nB;
    const long row0 = (long)blockIdx.y * 128;
    const long col0 = (long)blockIdx.x * 128;

    Ahi += zo * sAo + zi * sAi; Alo += zo * sAo + zi * sAi;
    Bhi += zo * sBo + zi * sBi; Blo += zo * sBo + zi * sBi;

    const int nch = K >> 6;

    auto load_chunk = [&](int ch, int stage) {
        const long k0 = (long)ch << 6;
#pragma unroll
        for (int i = 0; i < 16; i++) {
            const int u = tid + (i << 8);
            const int t = u >> 10;          // 0=Ahi 1=Alo 2=Bhi 3=Blo
            const int q = u & 1023;         // row*8 + seg
            const long r = q >> 3;
            const int sg = (q & 7) << 3;
            const bf16* p;
            if (t == 0)      p = Ahi + (row0 + r) * lda;
            else if (t == 1) p = Alo + (row0 + r) * lda;
            else if (t == 2) p = Bhi + (col0 + r) * ldb;
            else             p = Blo + (col0 + r) * ldb;
            uint32_t off = (uint32_t)(q << 4);            // row*128 + seg*16
            off ^= (off >> 3) & 0x70;                      // SW128
            cp16(sb + (uint32_t)stage * 65536u + (uint32_t)t * 16384u + off, p + k0 + sg);
        }
        CP_COMMIT();
    };

    float acc[4][4][4];
#pragma unroll
    for (int a = 0; a < 4; a++)
#pragma unroll
        for (int b = 0; b < 4; b++)
#pragma unroll
            for (int c = 0; c < 4; c++) acc[a][b][c] = 0.0f;

    load_chunk(0, 0);
    load_chunk(1, 1);

    for (int ch = 0; ch < nch; ch++) {
        if (ch + 2 < nch) {
            load_chunk(ch + 2, (ch + 2) % 3);
            CP_WAIT(2);
        } else {
            CP_WAIT(0);
        }
        __syncthreads();

        const uint32_t stg = sb + (uint32_t)(ch % 3) * 65536u;

#pragma unroll
        for (int ks = 0; ks < 4; ks++) {
            uint32_t ah[4][4], al[4][4], bh[2][4], bl[2][4];
#pragma unroll
            for (int mt = 0; mt < 4; mt++) {
                const int row = wm * 64 + mt * 16 + (lane & 15);
                const int colb = ks * 32 + ((lane >> 4) << 4);
                uint32_t off = (uint32_t)(row * 128 + colb);
                off ^= (off >> 3) & 0x70;
                ldm_x4(ah[mt], stg + off);
                ldm_x4(al[mt], stg + 16384u + off);
            }
#pragma unroll
            for (int np = 0; np < 2; np++) {
                const int row = wn * 32 + np * 16 + (lane & 7) + ((lane >> 4) << 3);
                const int colb = ks * 32 + (((lane >> 3) & 1) << 4);
                uint32_t off = (uint32_t)(row * 128 + colb);
                off ^= (off >> 3) & 0x70;
                ldm_x4(bh[np], stg + 32768u + off);
                ldm_x4(bl[np], stg + 49152u + off);
            }
#pragma unroll
            for (int mt = 0; mt < 4; mt++)
#pragma unroll
                for (int nt = 0; nt < 4; nt++) {
                    const uint32_t* bhp = &bh[nt >> 1][(nt & 1) * 2];
                    const uint32_t* blp = &bl[nt >> 1][(nt & 1) * 2];
                    mma_bf16(acc[mt][nt], ah[mt], bhp);
                    mma_bf16(acc[mt][nt], ah[mt], blp);
                    mma_bf16(acc[mt][nt], al[mt], bhp);
                }
        }
        __syncthreads();
    }

    // -------- epilogue --------
    float* Cz = C ? C + sC * z : nullptr;
    bf16* Hz = Chi ? Chi + sC * z : nullptr;
    bf16* Lz = Clo ? Clo + sC * z : nullptr;
    const float* bz = bias ? bias + (long)z * sBias : nullptr;

#pragma unroll
    for (int mt = 0; mt < 4; mt++)
#pragma unroll
        for (int nt = 0; nt < 4; nt++) {
            float* d = acc[mt][nt];
            const long gm = row0 + wm * 64 + mt * 16 + (lane >> 2);
            const long gn = col0 + wn * 32 + nt * 8 + (lane & 3) * 2;
            float b0 = 0.0f, b1 = 0.0f;
            if (bz) { b0 = __ldg(bz + gn); b1 = __ldg(bz + gn + 1); }
#pragma unroll
            for (int half = 0; half < 2; half++) {
                const long r = gm + half * 8;
                float x0 = d[half * 2 + 0] * alpha + b0;
                float x1 = d[half * 2 + 1] * alpha + b1;
                if (relu) { x0 = fmaxf(x0, 0.0f); x1 = fmaxf(x1, 0.0f); }
                const long o = r * ldc + gn;
                if (Cz) *(float2*)(Cz + o) = make_float2(x0, x1);
                if (Hz) {
                    bf16 h0, l0, h1, l1;
                    split2(x0, h0, l0); split2(x1, h1, l1);
                    uint32_t wh = (uint32_t)__bfloat16_as_ushort(h0) |
                                  ((uint32_t)__bfloat16_as_ushort(h1) << 16);
                    uint32_t wl = (uint32_t)__bfloat16_as_ushort(l0) |
                                  ((uint32_t)__bfloat16_as_ushort(l1) << 16);
                    *(uint32_t*)(Hz + o) = wh;
                    *(uint32_t*)(Lz + o) = wl;
                }
            }
        }
}

// ======================= transpose + split: [R][C] f32 -> [C][R] bf16 hi/lo ====
__global__ void __launch_bounds__(256)
transpose_split(const float* __restrict__ in, bf16* __restrict__ ohi, bf16* __restrict__ olo,
                int R, int Ccols, long sIn, long sOut)
{
    __shared__ float t[32][33];
    const float* ip = in + sIn * blockIdx.z;
    const int c0 = blockIdx.x * 32, r0 = blockIdx.y * 32;
    const int tx = threadIdx.x & 31, ty = threadIdx.x >> 5;
#pragma unroll
    for (int j = 0; j < 32; j += 8)
        t[ty + j][tx] = ip[(long)(r0 + ty + j) * Ccols + c0 + tx];
    __syncthreads();
#pragma unroll
    for (int j = 0; j < 32; j += 8) {
        float x = t[tx][ty + j];
        bf16 h, l; split2(x, h, l);
        long o = sOut * blockIdx.z + (long)(c0 + ty + j) * R + r0 + tx;
        ohi[o] = h; olo[o] = l;
    }
}

// ========== plain split of Wq|Wk|Wv into [qkv][l][in][out] bf16 hi/lo ==========
__global__ void __launch_bounds__(256)
split_plain_qkv(const float* __restrict__ Wq, const float* __restrict__ Wk,
                const float* __restrict__ Wv, bf16* __restrict__ ohi, bf16* __restrict__ olo)
{
    const long DDL = (long)NLAYER * DIM * DIM;
    const long idx = (long)blockIdx.x * blockDim.x + threadIdx.x;
    if (idx >= 3 * DDL) return;
    const int w = (int)(idx / DDL);
    const long r = idx - (long)w * DDL;
    const float* src = (w == 0) ? Wq : (w == 1) ? Wk : Wv;
    bf16 h, l; split2(src[r], h, l);
    ohi[idx] = h; olo[idx] = l;
}

// ======================= bf16 hi/lo pair transpose: [R][C] -> [C][R] ============
__global__ void __launch_bounds__(256)
transpose_pair(const bf16* __restrict__ ihi, const bf16* __restrict__ ilo,
               bf16* __restrict__ ohi, bf16* __restrict__ olo,
               int R, int Ccols, long sIn, long sOut)
{
    __shared__ unsigned short t[32][33];
    const int c0 = blockIdx.x * 32, r0 = blockIdx.y * 32;
    const int tx = threadIdx.x & 31, ty = threadIdx.x >> 5;
    const bf16* a = ihi + sIn * blockIdx.z;
    bf16* o = ohi + sOut * blockIdx.z;
#pragma unroll
    for (int pass = 0; pass < 2; pass++) {
#pragma unroll
        for (int j = 0; j < 32; j += 8)
            t[ty + j][tx] = __bfloat16_as_ushort(a[(long)(r0 + ty + j) * Ccols + c0 + tx]);
        __syncthreads();
#pragma unroll
        for (int j = 0; j < 32; j += 8)
            o[(long)(c0 + ty + j) * R + r0 + tx] = __ushort_as_bfloat16(t[tx][ty + j]);
        __syncthreads();
        a = ilo + sIn * blockIdx.z;
        o = olo + sOut * blockIdx.z;
    }
}

// ============= fused head bias: b'[l][qkv][a][e] = b_qkv . Wh[l][a][:,e] + bh ==
// reads wht (transposed Wh, [l][a][e][in], hi+lo) for coalesced dots.
__global__ void __launch_bounds__(256)
bias_head_kernel(const float* __restrict__ bq, const float* __restrict__ bk,
                 const float* __restrict__ bv, const float* __restrict__ bh,
                 const bf16* __restrict__ wht_hi, const bf16* __restrict__ wht_lo,
                 float* __restrict__ out)
{
    const int warpId = (blockIdx.x * blockDim.x + threadIdx.x) >> 5;
    const int lane = threadIdx.x & 31;
    const int total = NLAYER * 3 * NHEAD * DHEAD;
    if (warpId >= total) return;
    const int e = warpId & (DHEAD - 1);
    const int a = (warpId / DHEAD) & (NHEAD - 1);
    const int qkv = (warpId / (DHEAD * NHEAD)) % 3;
    const int l = warpId / (DHEAD * NHEAD * 3);
    const float* bsrc = ((qkv == 0) ? bq : (qkv == 1) ? bk : bv) + (long)l * DIM;
    const long wrow = (((long)l * NHEAD + a) * DHEAD + e) * DIM;
    float s = 0.0f;
    for (int i = lane; i < DIM; i += 32)
        s += bsrc[i] * (__bfloat162float(wht_hi[wrow + i]) + __bfloat162float(wht_lo[wrow + i]));
#pragma unroll
    for (int off = 16; off > 0; off >>= 1) s += __shfl_down_sync(0xFFFFFFFFu, s, off);
    if (lane == 0) out[warpId] = s + bh[((long)l * NHEAD + a) * DHEAD + e];
}

// ======== fused prologue misc: copy_split(hidden) ==============================
__global__ void __launch_bounds__(256)
prep_misc(const float* __restrict__ hidden, float* __restrict__ h,
          bf16* __restrict__ dhi, bf16* __restrict__ dlo)
{
    const int idx = blockIdx.x * blockDim.x + threadIdx.x;
    if (idx < SEQ * DIM) {
        float v = hidden[idx];
        h[idx] = v;
        bf16 hh, ll; split2(v, hh, ll);
        dhi[idx] = hh; dlo[idx] = ll;
    }
}

// ============ softmax over rows (bf16 hi/lo in, in-place hi/lo out) ============
__global__ void __launch_bounds__(256)
softmax_kernel(bf16* __restrict__ shi, bf16* __restrict__ slo)
{
    const size_t base = (size_t)blockIdx.x * SEQ;
    const int tid = threadIdx.x;

    float v[12];
    float mx = -1e30f;
#pragma unroll
    for (int i = 0; i < 12; i++) {
        const size_t o = base + tid + i * 256;
        v[i] = __bfloat162float(shi[o]) + __bfloat162float(slo[o]);
        mx = fmaxf(mx, v[i]);
    }
    __shared__ float red[256];
    red[tid] = mx;
    __syncthreads();
    for (int s = 128; s > 0; s >>= 1) {
        if (tid < s) red[tid] = fmaxf(red[tid], red[tid + s]);
        __syncthreads();
    }
    mx = red[0];
    __syncthreads();

    float sum = 0.0f;
#pragma unroll
    for (int i = 0; i < 12; i++) {
        v[i] = __expf(v[i] - mx);
        sum += v[i];
    }
    red[tid] = sum;
    __syncthreads();
    for (int s = 128; s > 0; s >>= 1) {
        if (tid < s) red[tid] += red[tid + s];
        __syncthreads();
    }
    const float inv = 1.0f / red[0];
#pragma unroll
    for (int i = 0; i < 12; i++) {
        float x = v[i] * inv;
        bf16 h, l; split2(x, h, l);
        const size_t o = base + tid + i * 256;
        shi[o] = h;
        slo[o] = l;
    }
}

// ======================= add + layernorm (emit f32 + hi/lo) ====================
__global__ void __launch_bounds__(256)
add_ln_kernel(float* __restrict__ h, const float* __restrict__ x,
              const float* __restrict__ g, const float* __restrict__ b,
              bf16* __restrict__ ohi, bf16* __restrict__ olo)
{
    const long row = blockIdx.x;
    float* hp = h + row * (long)DIM;
    const float* xp = x + row * (long)DIM;
    const int tid = threadIdx.x;

    float v[4];
    float sum = 0.0f;
#pragma unroll
    for (int i = 0; i < 4; i++) {
        const int c = tid + i * 256;
        v[i] = hp[c] + xp[c];
        sum += v[i];
    }
    __shared__ float red[256];
    red[tid] = sum;
    __syncthreads();
    for (int s = 128; s > 0; s >>= 1) {
        if (tid < s) red[tid] += red[tid + s];
        __syncthreads();
    }
    const float mu = red[0] * (1.0f / DIM);
    __syncthreads();

    float vs = 0.0f;
#pragma unroll
    for (int i = 0; i < 4; i++) {
        const float d = v[i] - mu;
        vs += d * d;
    }
    red[tid] = vs;
    __syncthreads();
    for (int s = 128; s > 0; s >>= 1) {
        if (tid < s) red[tid] += red[tid + s];
        __syncthreads();
    }
    const float inv = rsqrtf(red[0] * (1.0f / DIM) + LN_EPS);
    __syncthreads();
#pragma unroll
    for (int i = 0; i < 4; i++) {
        const int c = tid + i * 256;
        float y = g[c] * (v[i] - mu) * inv + b[c];
        hp[c] = y;
        bf16 hh, ll; split2(y, hh, ll);
        ohi[row * (long)DIM + c] = hh;
        olo[row * (long)DIM + c] = ll;
    }
}

// ======================= output heads =======================
__global__ void __launch_bounds__(256)
heads_kernel(const float* __restrict__ h, const float* __restrict__ Whead,
             const float* __restrict__ bhead, const int* __restrict__ nev,
             const int* __restrict__ nag, float* __restrict__ out, int total)
{
    const int warpId = (blockIdx.x * blockDim.x + threadIdx.x) >> 5;
    const int lane = threadIdx.x & 31;
    if (warpId >= total) return;
    const int NEv = *nev;
    const int NAg = *nag;
    int headIdx, token;
    if (warpId < 3 * NAg) {
        headIdx = warpId / NAg;
        token = NEv + warpId % NAg;
    } else {
        headIdx = 3;
        token = warpId - 3 * NAg;
    }
    const float* hr = h + (long)token * DIM;
    const float* w = Whead + (long)headIdx * DIM;
    float s = 0.0f;
    for (int i = lane; i < DIM; i += 32) s = fmaf(hr[i], w[i], s);
#pragma unroll
    for (int off = 16; off > 0; off >>= 1) s += __shfl_down_sync(0xFFFFFFFFu, s, off);
    if (lane == 0) out[warpId] = s + bhead[headIdx];
}

// ======================= host orchestration =======================
static void tcg(const bf16* Ahi, const bf16* Alo, int lda, long sAo, long sAi,
                const bf16* Bhi, const bf16* Blo, int ldb, long sBo, long sBi,
                const float* bias, long sBias, int nB,
                float* C, bf16* Chi, bf16* Clo, int ldc, long sC,
                int M, int N, int K, int batch, float alpha, int relu)
{
    dim3 grid(N / 128, M / 128, batch);
    mma_gemm<<<grid, 256, GSMEM_BYTES>>>(Ahi, Alo, lda, sAo, sAi, Bhi, Blo, ldb, sBo, sBi,
                                         bias, sBias, nB, C, Chi, Clo, ldc, sC, K, alpha, relu);
}

#define SYM(var, name) cudaGetSymbolAddress((void**)&var, name)

extern "C" void kernel_launch(void* const* d_in, const int* in_sizes, int n_in,
                              void* d_out, int out_size)
{
    const float* hidden = (const float*)d_in[0];
    const float* Wq = (const float*)d_in[1];
    const float* bq = (const float*)d_in[2];
    const float* Wk = (const float*)d_in[3];
    const float* bk = (const float*)d_in[4];
    const float* Wv = (const float*)d_in[5];
    const float* bv = (const float*)d_in[6];
    const float* Wh = (const float*)d_in[7];
    const float* bh = (const float*)d_in[8];
    const float* Wo = (const float*)d_in[9];
    const float* bo = (const float*)d_in[10];
    const float* g1 = (const float*)d_in[11];
    const float* b1n = (const float*)d_in[12];
    const float* g2 = (const float*)d_in[13];
    const float* b2n = (const float*)d_in[14];
    const float* Wf1 = (const float*)d_in[15];
    const float* bf1 = (const float*)d_in[16];
    const float* Wf2 = (const float*)d_in[17];
    const float* bf2 = (const float*)d_in[18];
    const float* Whead = (const float*)d_in[19];
    const float* bhead = (const float*)d_in[20];
    const int* n_events = (const int*)d_in[21];
    const int* n_agents = (const int*)d_in[22];
    (void)in_sizes; (void)n_in;

    cudaFuncSetAttribute(mma_gemm, cudaFuncAttributeMaxDynamicSharedMemorySize, GSMEM_BYTES);

    float *h, *tmp, *bprime;
    SYM(h, g_h); SYM(tmp, g_tmp); SYM(bprime, g_bprime);
    bf16 *h_hi, *h_lo, *qkvh_hi, *qkvh_lo;
    bf16 *vht_hi, *vht_lo, *ctx_hi, *ctx_lo, *f1_hi, *f1_lo, *at_hi, *at_lo;
    SYM(h_hi, g_h_hi); SYM(h_lo, g_h_lo);
    SYM(qkvh_hi, g_qkvh_hi); SYM(qkvh_lo, g_qkvh_lo);
    SYM(vht_hi, g_vht_hi); SYM(vht_lo, g_vht_lo);
    SYM(ctx_hi, g_ctx_hi); SYM(ctx_lo, g_ctx_lo);
    SYM(f1_hi, g_f1_hi); SYM(f1_lo, g_f1_lo);
    SYM(at_hi, g_at_hi); SYM(at_lo, g_at_lo);
    bf16 *wsplit_hi, *wsplit_lo, *wpt_hi, *wpt_lo, *wot_hi, *wot_lo, *wht_hi, *wht_lo;
    bf16 *w1t_hi, *w1t_lo, *w2t_hi, *w2t_lo;
    SYM(wsplit_hi, g_wsplit_hi); SYM(wsplit_lo, g_wsplit_lo);
    SYM(wpt_hi, g_wpt_hi); SYM(wpt_lo, g_wpt_lo);
    SYM(wot_hi, g_wot_hi); SYM(wot_lo, g_wot_lo);
    SYM(wht_hi, g_wht_hi); SYM(wht_lo, g_wht_lo);
    SYM(w1t_hi, g_w1t_hi); SYM(w1t_lo, g_w1t_lo);
    SYM(w2t_hi, g_w2t_hi); SYM(w2t_lo, g_w2t_lo);

    const long DD = (long)DIM * DIM;
    const long SD = (long)SEQ * DIM;
    const long SS = (long)SEQ * SEQ;
    const long SDh = (long)SEQ * DHEAD;
    const long WHL = (long)NHEAD * DHEAD * DIM;   // per-layer wht block
    const long HD = (long)DHEAD * DIM;            // per-head block

    // ---- prologue ----
    transpose_split<<<dim3(DIM / 32, DIM / 32, NLAYER), 256>>>(Wo, wot_hi, wot_lo, DIM, DIM, DD, DD);
    transpose_split<<<dim3(DHEAD / 32, DIM / 32, NLAYER * NHEAD), 256>>>(
        Wh, wht_hi, wht_lo, DIM, DHEAD, HD, HD);
    transpose_split<<<dim3(2 * DIM / 32, DIM / 32, NLAYER), 256>>>(Wf1, w1t_hi, w1t_lo, DIM, 2 * DIM, 2 * DD, 2 * DD);
    transpose_split<<<dim3(DIM / 32, 2 * DIM / 32, NLAYER), 256>>>(Wf2, w2t_hi, w2t_lo, 2 * DIM, DIM, 2 * DD, 2 * DD);
    {
        const long totalW = 3 * (long)NLAYER * DD;
        split_plain_qkv<<<(int)((totalW + 255) / 256), 256>>>(Wq, Wk, Wv, wsplit_hi, wsplit_lo);
    }
    prep_misc<<<(SEQ * DIM + 255) / 256, 256>>>(hidden, h, h_hi, h_lo);
    {
        const int totalB = NLAYER * 3 * NHEAD * DHEAD;
        bias_head_kernel<<<(totalB * 32 + 255) / 256, 256>>>(bq, bk, bv, bh, wht_hi, wht_lo, bprime);
    }
    // W'^T[qkv][l][a] = wht[l][a] (DHEADxDIM) x Wq/k/v (rows=in, cols=out->k)
    for (int qkv = 0; qkv < 3; qkv++) {
        tcg(wht_hi, wht_lo, DIM, WHL, HD,
            wsplit_hi + (long)qkv * NLAYER * DD, wsplit_lo + (long)qkv * NLAYER * DD, DIM, DD, 0,
            nullptr, 0, NHEAD,
            nullptr, wpt_hi + (long)qkv * NLAYER * WHL, wpt_lo + (long)qkv * NLAYER * WHL,
            DIM, HD, DHEAD, DIM, DIM, NLAYER * NHEAD, 1.0f, 0);
    }

    const float attn_scale = 1.0f / 16.0f;

    for (int l = 0; l < NLAYER; l++) {
        // fused QKV+head projections: qkvh[qkv][a] = h @ W'[l][qkv][a] + b'
        tcg(h_hi, h_lo, DIM, 0, 0,
            wpt_hi + l * WHL, wpt_lo + l * WHL, DIM, (long)NLAYER * WHL, HD,
            bprime + (long)l * 3 * NHEAD * DHEAD, DHEAD, NHEAD,
            nullptr, qkvh_hi, qkvh_lo, DHEAD, SDh, SEQ, DHEAD, DIM, 3 * NHEAD, 1.0f, 0);
        // Vh [head][t][e] -> [head][e][t]
        transpose_pair<<<dim3(DHEAD / 32, SEQ / 32, NHEAD), 256>>>(
            qkvh_hi + 2 * SD, qkvh_lo + 2 * SD, vht_hi, vht_lo, SEQ, DHEAD, SDh, SDh);
        // scores = scale * Qh @ Kh^T -> hi/lo bf16
        tcg(qkvh_hi, qkvh_lo, DHEAD, SDh, 0,
            qkvh_hi + SD, qkvh_lo + SD, DHEAD, SDh, 0,
            nullptr, 0, 1,
            nullptr, at_hi, at_lo, SEQ, SS, SEQ, SEQ, DHEAD, NHEAD, attn_scale, 0);
        // softmax in-place on hi/lo
        softmax_kernel<<<NHEAD * SEQ, 256>>>(at_hi, at_lo);
        // ctx = attn @ Vh -> [t][head*DHEAD+e]
        tcg(at_hi, at_lo, SEQ, SS, 0,
            vht_hi, vht_lo, SEQ, SDh, 0,
            nullptr, 0, 1,
            nullptr, ctx_hi, ctx_lo, DIM, DHEAD, SEQ, DHEAD, SEQ, NHEAD, 1.0f, 0);
        // attn_out = ctx @ Wo + bo -> f32 tmp
        tcg(ctx_hi, ctx_lo, DIM, 0, 0,
            wot_hi + l * DD, wot_lo + l * DD, DIM, 0, 0,
            bo + (long)l * DIM, 0, 1,
            tmp, nullptr, nullptr, DIM, 0, SEQ, DIM, DIM, 1, 1.0f, 0);
        add_ln_kernel<<<SEQ, 256>>>(h, tmp, g1 + (long)l * DIM, b1n + (long)l * DIM, h_hi, h_lo);
        // FFN
        tcg(h_hi, h_lo, DIM, 0, 0,
            w1t_hi + l * 2 * DD, w1t_lo + l * 2 * DD, DIM, 0, 0,
            bf1 + (long)l * 2 * DIM, 0, 1,
            nullptr, f1_hi, f1_lo, 2 * DIM, 0, SEQ, 2 * DIM, DIM, 1, 1.0f, 1);
        tcg(f1_hi, f1_lo, 2 * DIM, 0, 0,
            w2t_hi + l * 2 * DD, w2t_lo + l * 2 * DD, 2 * DIM, 0, 0,
            bf2 + (long)l * DIM, 0, 1,
            tmp, nullptr, nullptr, DIM, 0, SEQ, DIM, 2 * DIM, 1, 1.0f, 0);
        add_ln_kernel<<<SEQ, 256>>>(h, tmp, g2 + (long)l * DIM, b2n + (long)l * DIM, h_hi, h_lo);
    }

    const int blocks = (out_size * 32 + 255) / 256;
    heads_kernel<<<blocks, 256>>>(h, Whead, bhead, n_events, n_agents, (float*)d_out, out_size);
}

// round 9
// speedup vs baseline: 1.2300x; 1.0812x over previous
#include <cuda_runtime.h>
#include <cuda_bf16.h>
#include <cstdint>
#include <math.h>

#define SEQ 3072
#define DIM 1024
#define NHEAD 4
#define DHEAD 256
#define NLAYER 4
#define LN_EPS 1e-5f
typedef __nv_bfloat16 bf16;

// ======================= scratch (static device arrays) =======================
__device__ float g_h[SEQ * DIM];
__device__ float g_tmp[SEQ * DIM];
__device__ float g_split[2 * SEQ * DIM];                             // split-K partials

__device__ bf16 g_h_hi[SEQ * DIM],   g_h_lo[SEQ * DIM];
__device__ bf16 g_qkvh_hi[3 * SEQ * DIM], g_qkvh_lo[3 * SEQ * DIM];  // [qkv][head][t][e]
__device__ bf16 g_vht_hi[SEQ * DIM], g_vht_lo[SEQ * DIM];            // [head][e][t]
__device__ bf16 g_ctx_hi[SEQ * DIM], g_ctx_lo[SEQ * DIM];            // [t][head*DHEAD+e]
__device__ bf16 g_f1_hi[SEQ * 2 * DIM], g_f1_lo[SEQ * 2 * DIM];
__device__ bf16 g_at_hi[(size_t)NHEAD * SEQ * SEQ];                  // scores/attn hi
__device__ bf16 g_at_lo[(size_t)NHEAD * SEQ * SEQ];                  // scores/attn lo

// weights
__device__ bf16 g_wsplit_hi[3 * NLAYER * DIM * DIM], g_wsplit_lo[3 * NLAYER * DIM * DIM];
__device__ bf16 g_wpt_hi[3 * NLAYER * NHEAD * DHEAD * DIM];  // W'^T [qkv][l][a][e][in]
__device__ bf16 g_wpt_lo[3 * NLAYER * NHEAD * DHEAD * DIM];
__device__ bf16 g_wot_hi[NLAYER * DIM * DIM],  g_wot_lo[NLAYER * DIM * DIM];
__device__ bf16 g_wht_hi[NLAYER * NHEAD * DHEAD * DIM], g_wht_lo[NLAYER * NHEAD * DHEAD * DIM];
__device__ bf16 g_w1t_hi[NLAYER * DIM * 2 * DIM], g_w1t_lo[NLAYER * DIM * 2 * DIM];
__device__ bf16 g_w2t_hi[NLAYER * 2 * DIM * DIM], g_w2t_lo[NLAYER * 2 * DIM * DIM];
__device__ float g_bprime[NLAYER * 3 * NHEAD * DHEAD];       // [l][qkv][a][e]

// ======================= helpers =======================
__device__ __forceinline__ uint32_t s2u(const void* p) {
    uint32_t a;
    asm("{ .reg .u64 t; cvta.to.shared.u64 t, %1; cvt.u32.u64 %0, t; }" : "=r"(a) : "l"(p));
    return a;
}
__device__ __forceinline__ void split2(float x, bf16& h, bf16& l) {
    h = __float2bfloat16(x);
    l = __float2bfloat16(x - __bfloat162float(h));
}
__device__ __forceinline__ void cp16(uint32_t dst, const void* src) {
    asm volatile("cp.async.cg.shared.global [%0], [%1], 16;" :: "r"(dst), "l"(src) : "memory");
}
#define CP_COMMIT() asm volatile("cp.async.commit_group;" ::: "memory")
#define CP_WAIT(n)  asm volatile("cp.async.wait_group %0;" :: "n"(n) : "memory")

__device__ __forceinline__ void ldm_x4(uint32_t* r, uint32_t addr) {
    asm volatile("ldmatrix.sync.aligned.m8n8.x4.shared.b16 {%0,%1,%2,%3}, [%4];"
                 : "=r"(r[0]), "=r"(r[1]), "=r"(r[2]), "=r"(r[3]) : "r"(addr));
}
__device__ __forceinline__ void mma_bf16(float* c, const uint32_t* a, const uint32_t* b) {
    asm volatile(
        "mma.sync.aligned.m16n8k16.row.col.f32.bf16.bf16.f32 "
        "{%0,%1,%2,%3}, {%4,%5,%6,%7}, {%8,%9}, {%0,%1,%2,%3};"
        : "+f"(c[0]), "+f"(c[1]), "+f"(c[2]), "+f"(c[3])
        : "r"(a[0]), "r"(a[1]), "r"(a[2]), "r"(a[3]), "r"(b[0]), "r"(b[1]));
}

// ======================= split-bf16 mma.sync GEMM =======================
// Tile 128x128, BK=64 bf16, 3-stage cp.async pipeline, SW128 swizzle, occ 1.
// Optional split-K: grid.z = batch*kSplit, z = zb*kSplit + zs; each zs computes
// K/kSplit and writes f32 partials to Cpart[(zs*nzb + zb)*M*Npart + m*Npart + n].
#define GSMEM_BYTES 196608

__global__ void __launch_bounds__(256, 1)
mma_gemm(const bf16* __restrict__ Ahi, const bf16* __restrict__ Alo, int lda, long sAo, long sAi,
         const bf16* __restrict__ Bhi, const bf16* __restrict__ Blo, int ldb, long sBo, long sBi,
         const float* __restrict__ bias, long sBias, int nB,
         float* __restrict__ C, bf16* __restrict__ Chi, bf16* __restrict__ Clo,
         int ldc, long sC, int K, float alpha, int relu,
         int kSplit, float* __restrict__ Cpart)
{
    extern __shared__ char sm[];
    const uint32_t sb = s2u(sm);
    const int tid = threadIdx.x;
    const int wid = tid >> 5;
    const int lane = tid & 31;
    const int wm = wid >> 2;
    const int wn = wid & 3;
    int zb = blockIdx.z;
    int zs = 0;
    if (kSplit > 1) { zs = zb % kSplit; zb /= kSplit; }
    const int zo = zb / nB;
    const int zi = zb - zo * nB;
    const long row0 = (long)blockIdx.y * 128;
    const long col0 = (long)blockIdx.x * 128;

    const int Ksub = K / kSplit;
    const long koff = (long)zs * Ksub;

    Ahi += zo * sAo + zi * sAi + koff; Alo += zo * sAo + zi * sAi + koff;
    Bhi += zo * sBo + zi * sBi + koff; Blo += zo * sBo + zi * sBi + koff;

    const int nch = Ksub >> 6;

    auto load_chunk = [&](int ch, int stage) {
        const long k0 = (long)ch << 6;
#pragma unroll
        for (int i = 0; i < 16; i++) {
            const int u = tid + (i << 8);
            const int t = u >> 10;          // 0=Ahi 1=Alo 2=Bhi 3=Blo
            const int q = u & 1023;
            const long r = q >> 3;
            const int sg = (q & 7) << 3;
            const bf16* p;
            if (t == 0)      p = Ahi + (row0 + r) * lda;
            else if (t == 1) p = Alo + (row0 + r) * lda;
            else if (t == 2) p = Bhi + (col0 + r) * ldb;
            else             p = Blo + (col0 + r) * ldb;
            uint32_t off = (uint32_t)(q << 4);
            off ^= (off >> 3) & 0x70;
            cp16(sb + (uint32_t)stage * 65536u + (uint32_t)t * 16384u + off, p + k0 + sg);
        }
        CP_COMMIT();
    };

    float acc[4][4][4];
#pragma unroll
    for (int a = 0; a < 4; a++)
#pragma unroll
        for (int b = 0; b < 4; b++)
#pragma unroll
            for (int c = 0; c < 4; c++) acc[a][b][c] = 0.0f;

    load_chunk(0, 0);
    load_chunk(1, 1);

    for (int ch = 0; ch < nch; ch++) {
        if (ch + 2 < nch) {
            load_chunk(ch + 2, (ch + 2) % 3);
            CP_WAIT(2);
        } else {
            CP_WAIT(0);
        }
        __syncthreads();

        const uint32_t stg = sb + (uint32_t)(ch % 3) * 65536u;

#pragma unroll
        for (int ks = 0; ks < 4; ks++) {
            uint32_t ah[4][4], al[4][4], bh[2][4], bl[2][4];
#pragma unroll
            for (int mt = 0; mt < 4; mt++) {
                const int row = wm * 64 + mt * 16 + (lane & 15);
                const int colb = ks * 32 + ((lane >> 4) << 4);
                uint32_t off = (uint32_t)(row * 128 + colb);
                off ^= (off >> 3) & 0x70;
                ldm_x4(ah[mt], stg + off);
                ldm_x4(al[mt], stg + 16384u + off);
            }
#pragma unroll
            for (int np = 0; np < 2; np++) {
                const int row = wn * 32 + np * 16 + (lane & 7) + ((lane >> 4) << 3);
                const int colb = ks * 32 + (((lane >> 3) & 1) << 4);
                uint32_t off = (uint32_t)(row * 128 + colb);
                off ^= (off >> 3) & 0x70;
                ldm_x4(bh[np], stg + 32768u + off);
                ldm_x4(bl[np], stg + 49152u + off);
            }
#pragma unroll
            for (int mt = 0; mt < 4; mt++)
#pragma unroll
                for (int nt = 0; nt < 4; nt++) {
                    const uint32_t* bhp = &bh[nt >> 1][(nt & 1) * 2];
                    const uint32_t* blp = &bl[nt >> 1][(nt & 1) * 2];
                    mma_bf16(acc[mt][nt], ah[mt], bhp);
                    mma_bf16(acc[mt][nt], ah[mt], blp);
                    mma_bf16(acc[mt][nt], al[mt], bhp);
                }
        }
        __syncthreads();
    }

    // -------- epilogue --------
    if (kSplit > 1) {
        const long Npart = (long)gridDim.x * 128;
        const long M = (long)gridDim.y * 128;
        const int nzb = gridDim.z / kSplit;
        float* dst = Cpart + ((long)zs * nzb + zb) * M * Npart;
#pragma unroll
        for (int mt = 0; mt < 4; mt++)
#pragma unroll
            for (int nt = 0; nt < 4; nt++) {
                float* d = acc[mt][nt];
                const long gm = row0 + wm * 64 + mt * 16 + (lane >> 2);
                const long gn = col0 + wn * 32 + nt * 8 + (lane & 3) * 2;
#pragma unroll
                for (int half = 0; half < 2; half++) {
                    const long r = gm + half * 8;
                    *(float2*)(dst + r * Npart + gn) =
                        make_float2(d[half * 2 + 0] * alpha, d[half * 2 + 1] * alpha);
                }
            }
        return;
    }

    float* Cz = C ? C + sC * zb : nullptr;
    bf16* Hz = Chi ? Chi + sC * zb : nullptr;
    bf16* Lz = Clo ? Clo + sC * zb : nullptr;
    const float* bz = bias ? bias + (long)zb * sBias : nullptr;

#pragma unroll
    for (int mt = 0; mt < 4; mt++)
#pragma unroll
        for (int nt = 0; nt < 4; nt++) {
            float* d = acc[mt][nt];
            const long gm = row0 + wm * 64 + mt * 16 + (lane >> 2);
            const long gn = col0 + wn * 32 + nt * 8 + (lane & 3) * 2;
            float b0 = 0.0f, b1 = 0.0f;
            if (bz) { b0 = __ldg(bz + gn); b1 = __ldg(bz + gn + 1); }
#pragma unroll
            for (int half = 0; half < 2; half++) {
                const long r = gm + half * 8;
                float x0 = d[half * 2 + 0] * alpha + b0;
                float x1 = d[half * 2 + 1] * alpha + b1;
                if (relu) { x0 = fmaxf(x0, 0.0f); x1 = fmaxf(x1, 0.0f); }
                const long o = r * ldc + gn;
                if (Cz) *(float2*)(Cz + o) = make_float2(x0, x1);
                if (Hz) {
                    bf16 h0, l0, h1, l1;
                    split2(x0, h0, l0); split2(x1, h1, l1);
                    uint32_t wh = (uint32_t)__bfloat16_as_ushort(h0) |
                                  ((uint32_t)__bfloat16_as_ushort(h1) << 16);
                    uint32_t wl = (uint32_t)__bfloat16_as_ushort(l0) |
                                  ((uint32_t)__bfloat16_as_ushort(l1) << 16);
                    *(uint32_t*)(Hz + o) = wh;
                    *(uint32_t*)(Lz + o) = wl;
                }
            }
        }
}

// =============== split-K combine: out = p0 + p1 (+bias) -> f32 / hi/lo =========
// part layout: [zs][zb][m][Npart]; output C offset = zb*sC + m*ldc + n.
__global__ void __launch_bounds__(256)
combine2(const float* __restrict__ part, long perMat, long total,
         int Npart, const float* __restrict__ bias,
         float* __restrict__ outF, bf16* __restrict__ outHi, bf16* __restrict__ outLo,
         int ldc, long sC)
{
    const long i = ((long)blockIdx.x * blockDim.x + threadIdx.x) * 4;
    if (i >= total) return;
    const long zb = i / perMat;
    const long rem = i - zb * perMat;
    const long m = rem / Npart;
    const int n = (int)(rem - m * Npart);
    float4 p0 = *(const float4*)(part + i);
    float4 p1 = *(const float4*)(part + total + i);
    float x0 = p0.x + p1.x, x1 = p0.y + p1.y, x2 = p0.z + p1.z, x3 = p0.w + p1.w;
    if (bias) {
        x0 += __ldg(bias + n); x1 += __ldg(bias + n + 1);
        x2 += __ldg(bias + n + 2); x3 += __ldg(bias + n + 3);
    }
    const long o = zb * sC + m * ldc + n;
    if (outF) *(float4*)(outF + o) = make_float4(x0, x1, x2, x3);
    if (outHi) {
        bf16 h0, l0, h1, l1, h2, l2, h3, l3;
        split2(x0, h0, l0); split2(x1, h1, l1); split2(x2, h2, l2); split2(x3, h3, l3);
        uint2 wh, wl;
        wh.x = (uint32_t)__bfloat16_as_ushort(h0) | ((uint32_t)__bfloat16_as_ushort(h1) << 16);
        wh.y = (uint32_t)__bfloat16_as_ushort(h2) | ((uint32_t)__bfloat16_as_ushort(h3) << 16);
        wl.x = (uint32_t)__bfloat16_as_ushort(l0) | ((uint32_t)__bfloat16_as_ushort(l1) << 16);
        wl.y = (uint32_t)__bfloat16_as_ushort(l2) | ((uint32_t)__bfloat16_as_ushort(l3) << 16);
        *(uint2*)(outHi + o) = wh;
        *(uint2*)(outLo + o) = wl;
    }
}

// ======================= transpose + split: [R][C] f32 -> [C][R] bf16 hi/lo ====
__global__ void __launch_bounds__(256)
transpose_split(const float* __restrict__ in, bf16* __restrict__ ohi, bf16* __restrict__ olo,
                int R, int Ccols, long sIn, long sOut)
{
    __shared__ float t[32][33];
    const float* ip = in + sIn * blockIdx.z;
    const int c0 = blockIdx.x * 32, r0 = blockIdx.y * 32;
    const int tx = threadIdx.x & 31, ty = threadIdx.x >> 5;
#pragma unroll
    for (int j = 0; j < 32; j += 8)
        t[ty + j][tx] = ip[(long)(r0 + ty + j) * Ccols + c0 + tx];
    __syncthreads();
#pragma unroll
    for (int j = 0; j < 32; j += 8) {
        float x = t[tx][ty + j];
        bf16 h, l; split2(x, h, l);
        long o = sOut * blockIdx.z + (long)(c0 + ty + j) * R + r0 + tx;
        ohi[o] = h; olo[o] = l;
    }
}

// ========== plain split of Wq|Wk|Wv into [qkv][l][in][out] bf16 hi/lo ==========
__global__ void __launch_bounds__(256)
split_plain_qkv(const float* __restrict__ Wq, const float* __restrict__ Wk,
                const float* __restrict__ Wv, bf16* __restrict__ ohi, bf16* __restrict__ olo)
{
    const long DDL = (long)NLAYER * DIM * DIM;
    const long idx = (long)blockIdx.x * blockDim.x + threadIdx.x;
    if (idx >= 3 * DDL) return;
    const int w = (int)(idx / DDL);
    const long r = idx - (long)w * DDL;
    const float* src = (w == 0) ? Wq : (w == 1) ? Wk : Wv;
    bf16 h, l; split2(src[r], h, l);
    ohi[idx] = h; olo[idx] = l;
}

// ======================= bf16 hi/lo pair transpose: [R][C] -> [C][R] ============
__global__ void __launch_bounds__(256)
transpose_pair(const bf16* __restrict__ ihi, const bf16* __restrict__ ilo,
               bf16* __restrict__ ohi, bf16* __restrict__ olo,
               int R, int Ccols, long sIn, long sOut)
{
    __shared__ unsigned short t[32][33];
    const int c0 = blockIdx.x * 32, r0 = blockIdx.y * 32;
    const int tx = threadIdx.x & 31, ty = threadIdx.x >> 5;
    const bf16* a = ihi + sIn * blockIdx.z;
    bf16* o = ohi + sOut * blockIdx.z;
#pragma unroll
    for (int pass = 0; pass < 2; pass++) {
#pragma unroll
        for (int j = 0; j < 32; j += 8)
            t[ty + j][tx] = __bfloat16_as_ushort(a[(long)(r0 + ty + j) * Ccols + c0 + tx]);
        __syncthreads();
#pragma unroll
        for (int j = 0; j < 32; j += 8)
            o[(long)(c0 + ty + j) * R + r0 + tx] = __ushort_as_bfloat16(t[tx][ty + j]);
        __syncthreads();
        a = ilo + sIn * blockIdx.z;
        o = olo + sOut * blockIdx.z;
    }
}

// ============= fused head bias: b'[l][qkv][a][e] = b_qkv . Wh[l][a][:,e] + bh ==
__global__ void __launch_bounds__(256)
bias_head_kernel(const float* __restrict__ bq, const float* __restrict__ bk,
                 const float* __restrict__ bv, const float* __restrict__ bh,
                 const bf16* __restrict__ wht_hi, const bf16* __restrict__ wht_lo,
                 float* __restrict__ out)
{
    const int warpId = (blockIdx.x * blockDim.x + threadIdx.x) >> 5;
    const int lane = threadIdx.x & 31;
    const int total = NLAYER * 3 * NHEAD * DHEAD;
    if (warpId >= total) return;
    const int e = warpId & (DHEAD - 1);
    const int a = (warpId / DHEAD) & (NHEAD - 1);
    const int qkv = (warpId / (DHEAD * NHEAD)) % 3;
    const int l = warpId / (DHEAD * NHEAD * 3);
    const float* bsrc = ((qkv == 0) ? bq : (qkv == 1) ? bk : bv) + (long)l * DIM;
    const long wrow = (((long)l * NHEAD + a) * DHEAD + e) * DIM;
    float s = 0.0f;
    for (int i = lane; i < DIM; i += 32)
        s += bsrc[i] * (__bfloat162float(wht_hi[wrow + i]) + __bfloat162float(wht_lo[wrow + i]));
#pragma unroll
    for (int off = 16; off > 0; off >>= 1) s += __shfl_down_sync(0xFFFFFFFFu, s, off);
    if (lane == 0) out[warpId] = s + bh[((long)l * NHEAD + a) * DHEAD + e];
}

// ======== fused prologue misc: copy_split(hidden) ==============================
__global__ void __launch_bounds__(256)
prep_misc(const float* __restrict__ hidden, float* __restrict__ h,
          bf16* __restrict__ dhi, bf16* __restrict__ dlo)
{
    const int idx = blockIdx.x * blockDim.x + threadIdx.x;
    if (idx < SEQ * DIM) {
        float v = hidden[idx];
        h[idx] = v;
        bf16 hh, ll; split2(v, hh, ll);
        dhi[idx] = hh; dlo[idx] = ll;
    }
}

// ============ softmax over rows (bf16 hi/lo in, in-place hi/lo out) ============
__global__ void __launch_bounds__(256)
softmax_kernel(bf16* __restrict__ shi, bf16* __restrict__ slo)
{
    const size_t base = (size_t)blockIdx.x * SEQ;
    const int tid = threadIdx.x;

    float v[12];
    float mx = -1e30f;
#pragma unroll
    for (int i = 0; i < 12; i++) {
        const size_t o = base + tid + i * 256;
        v[i] = __bfloat162float(shi[o]) + __bfloat162float(slo[o]);
        mx = fmaxf(mx, v[i]);
    }
    __shared__ float red[256];
    red[tid] = mx;
    __syncthreads();
    for (int s = 128; s > 0; s >>= 1) {
        if (tid < s) red[tid] = fmaxf(red[tid], red[tid + s]);
        __syncthreads();
    }
    mx = red[0];
    __syncthreads();

    float sum = 0.0f;
#pragma unroll
    for (int i = 0; i < 12; i++) {
        v[i] = __expf(v[i] - mx);
        sum += v[i];
    }
    red[tid] = sum;
    __syncthreads();
    for (int s = 128; s > 0; s >>= 1) {
        if (tid < s) red[tid] += red[tid + s];
        __syncthreads();
    }
    const float inv = 1.0f / red[0];
#pragma unroll
    for (int i = 0; i < 12; i++) {
        float x = v[i] * inv;
        bf16 h, l; split2(x, h, l);
        const size_t o = base + tid + i * 256;
        shi[o] = h;
        slo[o] = l;
    }
}

// ======================= add + layernorm (emit f32 + hi/lo) ====================
__global__ void __launch_bounds__(256)
add_ln_kernel(float* __restrict__ h, const float* __restrict__ x,
              const float* __restrict__ g, const float* __restrict__ b,
              bf16* __restrict__ ohi, bf16* __restrict__ olo)
{
    const long row = blockIdx.x;
    float* hp = h + row * (long)DIM;
    const float* xp = x + row * (long)DIM;
    const int tid = threadIdx.x;

    float v[4];
    float sum = 0.0f;
#pragma unroll
    for (int i = 0; i < 4; i++) {
        const int c = tid + i * 256;
        v[i] = hp[c] + xp[c];
        sum += v[i];
    }
    __shared__ float red[256];
    red[tid] = sum;
    __syncthreads();
    for (int s = 128; s > 0; s >>= 1) {
        if (tid < s) red[tid] += red[tid + s];
        __syncthreads();
    }
    const float mu = red[0] * (1.0f / DIM);
    __syncthreads();

    float vs = 0.0f;
#pragma unroll
    for (int i = 0; i < 4; i++) {
        const float d = v[i] - mu;
        vs += d * d;
    }
    red[tid] = vs;
    __syncthreads();
    for (int s = 128; s > 0; s >>= 1) {
        if (tid < s) red[tid] += red[tid + s];
        __syncthreads();
    }
    const float inv = rsqrtf(red[0] * (1.0f / DIM) + LN_EPS);
    __syncthreads();
#pragma unroll
    for (int i = 0; i < 4; i++) {
        const int c = tid + i * 256;
        float y = g[c] * (v[i] - mu) * inv + b[c];
        hp[c] = y;
        bf16 hh, ll; split2(y, hh, ll);
        ohi[row * (long)DIM + c] = hh;
        olo[row * (long)DIM + c] = ll;
    }
}

// ======================= output heads =======================
__global__ void __launch_bounds__(256)
heads_kernel(const float* __restrict__ h, const float* __restrict__ Whead,
             const float* __restrict__ bhead, const int* __restrict__ nev,
             const int* __restrict__ nag, float* __restrict__ out, int total)
{
    const int warpId = (blockIdx.x * blockDim.x + threadIdx.x) >> 5;
    const int lane = threadIdx.x & 31;
    if (warpId >= total) return;
    const int NEv = *nev;
    const int NAg = *nag;
    int headIdx, token;
    if (warpId < 3 * NAg) {
        headIdx = warpId / NAg;
        token = NEv + warpId % NAg;
    } else {
        headIdx = 3;
        token = warpId - 3 * NAg;
    }
    const float* hr = h + (long)token * DIM;
    const float* w = Whead + (long)headIdx * DIM;
    float s = 0.0f;
    for (int i = lane; i < DIM; i += 32) s = fmaf(hr[i], w[i], s);
#pragma unroll
    for (int off = 16; off > 0; off >>= 1) s += __shfl_down_sync(0xFFFFFFFFu, s, off);
    if (lane == 0) out[warpId] = s + bhead[headIdx];
}

// ======================= host orchestration =======================
static void tcg(const bf16* Ahi, const bf16* Alo, int lda, long sAo, long sAi,
                const bf16* Bhi, const bf16* Blo, int ldb, long sBo, long sBi,
                const float* bias, long sBias, int nB,
                float* C, bf16* Chi, bf16* Clo, int ldc, long sC,
                int M, int N, int K, int batch, float alpha, int relu,
                int kSplit = 1, float* Cpart = nullptr)
{
    dim3 grid(N / 128, M / 128, batch * kSplit);
    mma_gemm<<<grid, 256, GSMEM_BYTES>>>(Ahi, Alo, lda, sAo, sAi, Bhi, Blo, ldb, sBo, sBi,
                                         bias, sBias, nB, C, Chi, Clo, ldc, sC, K, alpha, relu,
                                         kSplit, Cpart);
}

#define SYM(var, name) cudaGetSymbolAddress((void**)&var, name)

extern "C" void kernel_launch(void* const* d_in, const int* in_sizes, int n_in,
                              void* d_out, int out_size)
{
    const float* hidden = (const float*)d_in[0];
    const float* Wq = (const float*)d_in[1];
    const float* bq = (const float*)d_in[2];
    const float* Wk = (const float*)d_in[3];
    const float* bk = (const float*)d_in[4];
    const float* Wv = (const float*)d_in[5];
    const float* bv = (const float*)d_in[6];
    const float* Wh = (const float*)d_in[7];
    const float* bh = (const float*)d_in[8];
    const float* Wo = (const float*)d_in[9];
    const float* bo = (const float*)d_in[10];
    const float* g1 = (const float*)d_in[11];
    const float* b1n = (const float*)d_in[12];
    const float* g2 = (const float*)d_in[13];
    const float* b2n = (const float*)d_in[14];
    const float* Wf1 = (const float*)d_in[15];
    const float* bf1 = (const float*)d_in[16];
    const float* Wf2 = (const float*)d_in[17];
    const float* bf2 = (const float*)d_in[18];
    const float* Whead = (const float*)d_in[19];
    const float* bhead = (const float*)d_in[20];
    const int* n_events = (const int*)d_in[21];
    const int* n_agents = (const int*)d_in[22];
    (void)in_sizes; (void)n_in;

    cudaFuncSetAttribute(mma_gemm, cudaFuncAttributeMaxDynamicSharedMemorySize, GSMEM_BYTES);

    float *h, *tmp, *bprime, *spl;
    SYM(h, g_h); SYM(tmp, g_tmp); SYM(bprime, g_bprime); SYM(spl, g_split);
    bf16 *h_hi, *h_lo, *qkvh_hi, *qkvh_lo;
    bf16 *vht_hi, *vht_lo, *ctx_hi, *ctx_lo, *f1_hi, *f1_lo, *at_hi, *at_lo;
    SYM(h_hi, g_h_hi); SYM(h_lo, g_h_lo);
    SYM(qkvh_hi, g_qkvh_hi); SYM(qkvh_lo, g_qkvh_lo);
    SYM(vht_hi, g_vht_hi); SYM(vht_lo, g_vht_lo);
    SYM(ctx_hi, g_ctx_hi); SYM(ctx_lo, g_ctx_lo);
    SYM(f1_hi, g_f1_hi); SYM(f1_lo, g_f1_lo);
    SYM(at_hi, g_at_hi); SYM(at_lo, g_at_lo);
    bf16 *wsplit_hi, *wsplit_lo, *wpt_hi, *wpt_lo, *wot_hi, *wot_lo, *wht_hi, *wht_lo;
    bf16 *w1t_hi, *w1t_lo, *w2t_hi, *w2t_lo;
    SYM(wsplit_hi, g_wsplit_hi); SYM(wsplit_lo, g_wsplit_lo);
    SYM(wpt_hi, g_wpt_hi); SYM(wpt_lo, g_wpt_lo);
    SYM(wot_hi, g_wot_hi); SYM(wot_lo, g_wot_lo);
    SYM(wht_hi, g_wht_hi); SYM(wht_lo, g_wht_lo);
    SYM(w1t_hi, g_w1t_hi); SYM(w1t_lo, g_w1t_lo);
    SYM(w2t_hi, g_w2t_hi); SYM(w2t_lo, g_w2t_lo);

    const long DD = (long)DIM * DIM;
    const long SD = (long)SEQ * DIM;
    const long SS = (long)SEQ * SEQ;
    const long SDh = (long)SEQ * DHEAD;
    const long WHL = (long)NHEAD * DHEAD * DIM;
    const long HD = (long)DHEAD * DIM;

    // ---- prologue ----
    transpose_split<<<dim3(DIM / 32, DIM / 32, NLAYER), 256>>>(Wo, wot_hi, wot_lo, DIM, DIM, DD, DD);
    transpose_split<<<dim3(DHEAD / 32, DIM / 32, NLAYER * NHEAD), 256>>>(
        Wh, wht_hi, wht_lo, DIM, DHEAD, HD, HD);
    transpose_split<<<dim3(2 * DIM / 32, DIM / 32, NLAYER), 256>>>(Wf1, w1t_hi, w1t_lo, DIM, 2 * DIM, 2 * DD, 2 * DD);
    transpose_split<<<dim3(DIM / 32, 2 * DIM / 32, NLAYER), 256>>>(Wf2, w2t_hi, w2t_lo, 2 * DIM, DIM, 2 * DD, 2 * DD);
    {
        const long totalW = 3 * (long)NLAYER * DD;
        split_plain_qkv<<<(int)((totalW + 255) / 256), 256>>>(Wq, Wk, Wv, wsplit_hi, wsplit_lo);
    }
    prep_misc<<<(SEQ * DIM + 255) / 256, 256>>>(hidden, h, h_hi, h_lo);
    {
        const int totalB = NLAYER * 3 * NHEAD * DHEAD;
        bias_head_kernel<<<(totalB * 32 + 255) / 256, 256>>>(bq, bk, bv, bh, wht_hi, wht_lo, bprime);
    }
    for (int qkv = 0; qkv < 3; qkv++) {
        tcg(wht_hi, wht_lo, DIM, WHL, HD,
            wsplit_hi + (long)qkv * NLAYER * DD, wsplit_lo + (long)qkv * NLAYER * DD, DIM, DD, 0,
            nullptr, 0, NHEAD,
            nullptr, wpt_hi + (long)qkv * NLAYER * WHL, wpt_lo + (long)qkv * NLAYER * WHL,
            DIM, HD, DHEAD, DIM, DIM, NLAYER * NHEAD, 1.0f, 0);
    }

    const float attn_scale = 1.0f / 16.0f;

    for (int l = 0; l < NLAYER; l++) {
        // fused QKV+head projections: qkvh[qkv][a] = h @ W'[l][qkv][a] + b'
        tcg(h_hi, h_lo, DIM, 0, 0,
            wpt_hi + l * WHL, wpt_lo + l * WHL, DIM, (long)NLAYER * WHL, HD,
            bprime + (long)l * 3 * NHEAD * DHEAD, DHEAD, NHEAD,
            nullptr, qkvh_hi, qkvh_lo, DHEAD, SDh, SEQ, DHEAD, DIM, 3 * NHEAD, 1.0f, 0);
        // Vh [head][t][e] -> [head][e][t]
        transpose_pair<<<dim3(DHEAD / 32, SEQ / 32, NHEAD), 256>>>(
            qkvh_hi + 2 * SD, qkvh_lo + 2 * SD, vht_hi, vht_lo, SEQ, DHEAD, SDh, SDh);
        // scores = scale * Qh @ Kh^T -> hi/lo bf16
        tcg(qkvh_hi, qkvh_lo, DHEAD, SDh, 0,
            qkvh_hi + SD, qkvh_lo + SD, DHEAD, SDh, 0,
            nullptr, 0, 1,
            nullptr, at_hi, at_lo, SEQ, SS, SEQ, SEQ, DHEAD, NHEAD, attn_scale, 0);
        // softmax in-place on hi/lo
        softmax_kernel<<<NHEAD * SEQ, 256>>>(at_hi, at_lo);
        // ctx = attn @ Vh  (split-K=2, partials -> combine to hi/lo [t][a*DHEAD+e])
        tcg(at_hi, at_lo, SEQ, SS, 0,
            vht_hi, vht_lo, SEQ, SDh, 0,
            nullptr, 0, 1,
            nullptr, nullptr, nullptr, 0, 0, SEQ, DHEAD, SEQ, NHEAD, 1.0f, 0,
            2, spl);
        {
            const long total = (long)NHEAD * SEQ * DHEAD;
            combine2<<<(int)((total / 4 + 255) / 256), 256>>>(
                spl, SDh, total, DHEAD, nullptr,
                nullptr, ctx_hi, ctx_lo, DIM, DHEAD);
        }
        // attn_out = ctx @ Wo + bo (split-K=2 -> f32 tmp)
        tcg(ctx_hi, ctx_lo, DIM, 0, 0,
            wot_hi + l * DD, wot_lo + l * DD, DIM, 0, 0,
            nullptr, 0, 1,
            nullptr, nullptr, nullptr, 0, 0, SEQ, DIM, DIM, 1, 1.0f, 0,
            2, spl);
        combine2<<<(int)((SD / 4 + 255) / 256), 256>>>(
            spl, SD, SD, DIM, bo + (long)l * DIM,
            tmp, nullptr, nullptr, DIM, 0);
        add_ln_kernel<<<SEQ, 256>>>(h, tmp, g1 + (long)l * DIM, b1n + (long)l * DIM, h_hi, h_lo);
        // FFN
        tcg(h_hi, h_lo, DIM, 0, 0,
            w1t_hi + l * 2 * DD, w1t_lo + l * 2 * DD, DIM, 0, 0,
            bf1 + (long)l * 2 * DIM, 0, 1,
            nullptr, f1_hi, f1_lo, 2 * DIM, 0, SEQ, 2 * DIM, DIM, 1, 1.0f, 1);
        tcg(f1_hi, f1_lo, 2 * DIM, 0, 0,
            w2t_hi + l * 2 * DD, w2t_lo + l * 2 * DD, 2 * DIM, 0, 0,
            nullptr, 0, 1,
            nullptr, nullptr, nullptr, 0, 0, SEQ, DIM, 2 * DIM, 1, 1.0f, 0,
            2, spl);
        combine2<<<(int)((SD / 4 + 255) / 256), 256>>>(
            spl, SD, SD, DIM, bf2 + (long)l * DIM,
            tmp, nullptr, nullptr, DIM, 0);
        add_ln_kernel<<<SEQ, 256>>>(h, tmp, g2 + (long)l * DIM, b2n + (long)l * DIM, h_hi, h_lo);
    }

    const int blocks = (out_size * 32 + 255) / 256;
    heads_kernel<<<blocks, 256>>>(h, Whead, bhead, n_events, n_agents, (float*)d_out, out_size);
}

// round 10
// speedup vs baseline: 1.6165x; 1.3142x over previous
#include <cuda_runtime.h>
#include <cuda_fp16.h>
#include <cstdint>
#include <math.h>

#define SEQ 3072
#define DIM 1024
#define NHEAD 4
#define DHEAD 256
#define NLAYER 4
#define LN_EPS 1e-5f
typedef __half f16;

// ======================= scratch (static device arrays) =======================
__device__ float g_h[SEQ * DIM];
__device__ float g_tmp[SEQ * DIM];
__device__ float g_split[2 * SEQ * DIM];                             // split-K partials

__device__ f16 g_h_hi[SEQ * DIM],   g_h_lo[SEQ * DIM];
__device__ f16 g_qkvh_hi[3 * SEQ * DIM], g_qkvh_lo[3 * SEQ * DIM];  // [qkv][head][t][e]
__device__ f16 g_vht_hi[SEQ * DIM];                                  // [head][e][t] (B-side: hi only)
__device__ f16 g_ctx_hi[SEQ * DIM], g_ctx_lo[SEQ * DIM];            // [t][head*DHEAD+e]
__device__ f16 g_f1_hi[SEQ * 2 * DIM], g_f1_lo[SEQ * 2 * DIM];
__device__ f16 g_at_hi[(size_t)NHEAD * SEQ * SEQ];                  // scores/attn hi
__device__ f16 g_at_lo[(size_t)NHEAD * SEQ * SEQ];                  // scores/attn lo

// weights
__device__ f16 g_wsplit_hi[3 * NLAYER * DIM * DIM], g_wsplit_lo[3 * NLAYER * DIM * DIM];
__device__ f16 g_wpt_hi[3 * NLAYER * NHEAD * DHEAD * DIM];  // W'^T [qkv][l][a][e][in]
__device__ f16 g_wpt_lo[3 * NLAYER * NHEAD * DHEAD * DIM];
__device__ f16 g_wot_hi[NLAYER * DIM * DIM],  g_wot_lo[NLAYER * DIM * DIM];
__device__ f16 g_wht_hi[NLAYER * NHEAD * DHEAD * DIM], g_wht_lo[NLAYER * NHEAD * DHEAD * DIM];
__device__ f16 g_w1t_hi[NLAYER * DIM * 2 * DIM], g_w1t_lo[NLAYER * DIM * 2 * DIM];
__device__ f16 g_w2t_hi[NLAYER * 2 * DIM * DIM], g_w2t_lo[NLAYER * 2 * DIM * DIM];
__device__ float g_bprime[NLAYER * 3 * NHEAD * DHEAD];       // [l][qkv][a][e]

// ======================= helpers =======================
__device__ __forceinline__ uint32_t s2u(const void* p) {
    uint32_t a;
    asm("{ .reg .u64 t; cvta.to.shared.u64 t, %1; cvt.u32.u64 %0, t; }" : "=r"(a) : "l"(p));
    return a;
}
__device__ __forceinline__ void split2(float x, f16& h, f16& l) {
    h = __float2half_rn(x);
    l = __float2half_rn(x - __half2float(h));
}
__device__ __forceinline__ void cp16(uint32_t dst, const void* src) {
    asm volatile("cp.async.cg.shared.global [%0], [%1], 16;" :: "r"(dst), "l"(src) : "memory");
}
#define CP_COMMIT() asm volatile("cp.async.commit_group;" ::: "memory")
#define CP_WAIT(n)  asm volatile("cp.async.wait_group %0;" :: "n"(n) : "memory")

__device__ __forceinline__ void ldm_x4(uint32_t* r, uint32_t addr) {
    asm volatile("ldmatrix.sync.aligned.m8n8.x4.shared.b16 {%0,%1,%2,%3}, [%4];"
                 : "=r"(r[0]), "=r"(r[1]), "=r"(r[2]), "=r"(r[3]) : "r"(addr));
}
__device__ __forceinline__ void mma_f16(float* c, const uint32_t* a, const uint32_t* b) {
    asm volatile(
        "mma.sync.aligned.m16n8k16.row.col.f32.f16.f16.f32 "
        "{%0,%1,%2,%3}, {%4,%5,%6,%7}, {%8,%9}, {%0,%1,%2,%3};"
        : "+f"(c[0]), "+f"(c[1]), "+f"(c[2]), "+f"(c[3])
        : "r"(a[0]), "r"(a[1]), "r"(a[2]), "r"(a[3]), "r"(b[0]), "r"(b[1]));
}

// ======================= split-fp16 mma.sync GEMM =======================
// C[m][n] = alpha * sum_k A[m][k]*B[n][k] + bias[n]
// A given as hi/lo fp16 (exact to ~2^-22), B as hi only (error ~2^-12 rel).
// Tile 128x128, BK=64, 3-stage cp.async (48KB/stage: Ahi|Alo|Bhi), SW128, occ 1.
// Optional split-K: grid.z = batch*kSplit; partials Cpart[(zs*nzb+zb)*M*Npart + ...].
#define GSMEM_BYTES 147456
#define STAGE_BYTES 49152u

__global__ void __launch_bounds__(256, 1)
mma_gemm(const f16* __restrict__ Ahi, const f16* __restrict__ Alo, int lda, long sAo, long sAi,
         const f16* __restrict__ Bhi, int ldb, long sBo, long sBi,
         const float* __restrict__ bias, long sBias, int nB,
         float* __restrict__ C, f16* __restrict__ Chi, f16* __restrict__ Clo,
         int ldc, long sC, int K, float alpha, int relu,
         int kSplit, float* __restrict__ Cpart)
{
    extern __shared__ char sm[];
    const uint32_t sb = s2u(sm);
    const int tid = threadIdx.x;
    const int wid = tid >> 5;
    const int lane = tid & 31;
    const int wm = wid >> 2;
    const int wn = wid & 3;
    int zb = blockIdx.z;
    int zs = 0;
    if (kSplit > 1) { zs = zb % kSplit; zb /= kSplit; }
    const int zo = zb / nB;
    const int zi = zb - zo * nB;
    const long row0 = (long)blockIdx.y * 128;
    const long col0 = (long)blockIdx.x * 128;

    const int Ksub = K / kSplit;
    const long koff = (long)zs * Ksub;

    Ahi += zo * sAo + zi * sAi + koff; Alo += zo * sAo + zi * sAi + koff;
    Bhi += zo * sBo + zi * sBi + koff;

    const int nch = Ksub >> 6;

    auto load_chunk = [&](int ch, int stage) {
        const long k0 = (long)ch << 6;
#pragma unroll
        for (int i = 0; i < 12; i++) {
            const int u = tid + (i << 8);
            const int t = u >> 10;          // 0=Ahi 1=Alo 2=Bhi
            const int q = u & 1023;         // row*8 + seg
            const long r = q >> 3;
            const int sg = (q & 7) << 3;
            const f16* p;
            if (t == 0)      p = Ahi + (row0 + r) * lda;
            else if (t == 1) p = Alo + (row0 + r) * lda;
            else             p = Bhi + (col0 + r) * ldb;
            uint32_t off = (uint32_t)(q << 4);
            off ^= (off >> 3) & 0x70;
            cp16(sb + (uint32_t)stage * STAGE_BYTES + (uint32_t)t * 16384u + off, p + k0 + sg);
        }
        CP_COMMIT();
    };

    float acc[4][4][4];
#pragma unroll
    for (int a = 0; a < 4; a++)
#pragma unroll
        for (int b = 0; b < 4; b++)
#pragma unroll
            for (int c = 0; c < 4; c++) acc[a][b][c] = 0.0f;

    load_chunk(0, 0);
    load_chunk(1, 1);

    for (int ch = 0; ch < nch; ch++) {
        if (ch + 2 < nch) {
            load_chunk(ch + 2, (ch + 2) % 3);
            CP_WAIT(2);
        } else {
            CP_WAIT(0);
        }
        __syncthreads();

        const uint32_t stg = sb + (uint32_t)(ch % 3) * STAGE_BYTES;

#pragma unroll
        for (int ks = 0; ks < 4; ks++) {
            uint32_t ah[4][4], al[4][4], bh[2][4];
#pragma unroll
            for (int mt = 0; mt < 4; mt++) {
                const int row = wm * 64 + mt * 16 + (lane & 15);
                const int colb = ks * 32 + ((lane >> 4) << 4);
                uint32_t off = (uint32_t)(row * 128 + colb);
                off ^= (off >> 3) & 0x70;
                ldm_x4(ah[mt], stg + off);
                ldm_x4(al[mt], stg + 16384u + off);
            }
#pragma unroll
            for (int np = 0; np < 2; np++) {
                const int row = wn * 32 + np * 16 + (lane & 7) + ((lane >> 4) << 3);
                const int colb = ks * 32 + (((lane >> 3) & 1) << 4);
                uint32_t off = (uint32_t)(row * 128 + colb);
                off ^= (off >> 3) & 0x70;
                ldm_x4(bh[np], stg + 32768u + off);
            }
#pragma unroll
            for (int mt = 0; mt < 4; mt++)
#pragma unroll
                for (int nt = 0; nt < 4; nt++) {
                    const uint32_t* bhp = &bh[nt >> 1][(nt & 1) * 2];
                    mma_f16(acc[mt][nt], ah[mt], bhp);
                    mma_f16(acc[mt][nt], al[mt], bhp);
                }
        }
        __syncthreads();
    }

    // -------- epilogue --------
    if (kSplit > 1) {
        const long Npart = (long)gridDim.x * 128;
        const long M = (long)gridDim.y * 128;
        const int nzb = gridDim.z / kSplit;
        float* dst = Cpart + ((long)zs * nzb + zb) * M * Npart;
#pragma unroll
        for (int mt = 0; mt < 4; mt++)
#pragma unroll
            for (int nt = 0; nt < 4; nt++) {
                float* d = acc[mt][nt];
                const long gm = row0 + wm * 64 + mt * 16 + (lane >> 2);
                const long gn = col0 + wn * 32 + nt * 8 + (lane & 3) * 2;
#pragma unroll
                for (int half = 0; half < 2; half++) {
                    const long r = gm + half * 8;
                    *(float2*)(dst + r * Npart + gn) =
                        make_float2(d[half * 2 + 0] * alpha, d[half * 2 + 1] * alpha);
                }
            }
        return;
    }

    float* Cz = C ? C + sC * zb : nullptr;
    f16* Hz = Chi ? Chi + sC * zb : nullptr;
    f16* Lz = Clo ? Clo + sC * zb : nullptr;
    const float* bz = bias ? bias + (long)zb * sBias : nullptr;

#pragma unroll
    for (int mt = 0; mt < 4; mt++)
#pragma unroll
        for (int nt = 0; nt < 4; nt++) {
            float* d = acc[mt][nt];
            const long gm = row0 + wm * 64 + mt * 16 + (lane >> 2);
            const long gn = col0 + wn * 32 + nt * 8 + (lane & 3) * 2;
            float b0 = 0.0f, b1 = 0.0f;
            if (bz) { b0 = __ldg(bz + gn); b1 = __ldg(bz + gn + 1); }
#pragma unroll
            for (int half = 0; half < 2; half++) {
                const long r = gm + half * 8;
                float x0 = d[half * 2 + 0] * alpha + b0;
                float x1 = d[half * 2 + 1] * alpha + b1;
                if (relu) { x0 = fmaxf(x0, 0.0f); x1 = fmaxf(x1, 0.0f); }
                const long o = r * ldc + gn;
                if (Cz) *(float2*)(Cz + o) = make_float2(x0, x1);
                if (Hz) {
                    f16 h0, l0, h1, l1;
                    split2(x0, h0, l0); split2(x1, h1, l1);
                    uint32_t wh = (uint32_t)__half_as_ushort(h0) |
                                  ((uint32_t)__half_as_ushort(h1) << 16);
                    uint32_t wl = (uint32_t)__half_as_ushort(l0) |
                                  ((uint32_t)__half_as_ushort(l1) << 16);
                    *(uint32_t*)(Hz + o) = wh;
                    if (Lz) *(uint32_t*)(Lz + o) = wl;
                }
            }
        }
}

// =============== split-K combine: out = p0 + p1 (+bias) -> f32 / hi/lo =========
__global__ void __launch_bounds__(256)
combine2(const float* __restrict__ part, long perMat, long total,
         int Npart, const float* __restrict__ bias,
         float* __restrict__ outF, f16* __restrict__ outHi, f16* __restrict__ outLo,
         int ldc, long sC)
{
    const long i = ((long)blockIdx.x * blockDim.x + threadIdx.x) * 4;
    if (i >= total) return;
    const long zb = i / perMat;
    const long rem = i - zb * perMat;
    const long m = rem / Npart;
    const int n = (int)(rem - m * Npart);
    float4 p0 = *(const float4*)(part + i);
    float4 p1 = *(const float4*)(part + total + i);
    float x0 = p0.x + p1.x, x1 = p0.y + p1.y, x2 = p0.z + p1.z, x3 = p0.w + p1.w;
    if (bias) {
        x0 += __ldg(bias + n); x1 += __ldg(bias + n + 1);
        x2 += __ldg(bias + n + 2); x3 += __ldg(bias + n + 3);
    }
    const long o = zb * sC + m * ldc + n;
    if (outF) *(float4*)(outF + o) = make_float4(x0, x1, x2, x3);
    if (outHi) {
        f16 h0, l0, h1, l1, h2, l2, h3, l3;
        split2(x0, h0, l0); split2(x1, h1, l1); split2(x2, h2, l2); split2(x3, h3, l3);
        uint2 wh, wl;
        wh.x = (uint32_t)__half_as_ushort(h0) | ((uint32_t)__half_as_ushort(h1) << 16);
        wh.y = (uint32_t)__half_as_ushort(h2) | ((uint32_t)__half_as_ushort(h3) << 16);
        wl.x = (uint32_t)__half_as_ushort(l0) | ((uint32_t)__half_as_ushort(l1) << 16);
        wl.y = (uint32_t)__half_as_ushort(l2) | ((uint32_t)__half_as_ushort(l3) << 16);
        *(uint2*)(outHi + o) = wh;
        *(uint2*)(outLo + o) = wl;
    }
}

// ======================= transpose + split: [R][C] f32 -> [C][R] f16 hi/lo =====
__global__ void __launch_bounds__(256)
transpose_split(const float* __restrict__ in, f16* __restrict__ ohi, f16* __restrict__ olo,
                int R, int Ccols, long sIn, long sOut)
{
    __shared__ float t[32][33];
    const float* ip = in + sIn * blockIdx.z;
    const int c0 = blockIdx.x * 32, r0 = blockIdx.y * 32;
    const int tx = threadIdx.x & 31, ty = threadIdx.x >> 5;
#pragma unroll
    for (int j = 0; j < 32; j += 8)
        t[ty + j][tx] = ip[(long)(r0 + ty + j) * Ccols + c0 + tx];
    __syncthreads();
#pragma unroll
    for (int j = 0; j < 32; j += 8) {
        float x = t[tx][ty + j];
        f16 h, l; split2(x, h, l);
        long o = sOut * blockIdx.z + (long)(c0 + ty + j) * R + r0 + tx;
        ohi[o] = h; olo[o] = l;
    }
}

// ========== plain split of Wq|Wk|Wv into [qkv][l][in][out] f16 hi/lo ==========
__global__ void __launch_bounds__(256)
split_plain_qkv(const float* __restrict__ Wq, const float* __restrict__ Wk,
                const float* __restrict__ Wv, f16* __restrict__ ohi, f16* __restrict__ olo)
{
    const long DDL = (long)NLAYER * DIM * DIM;
    const long idx = (long)blockIdx.x * blockDim.x + threadIdx.x;
    if (idx >= 3 * DDL) return;
    const int w = (int)(idx / DDL);
    const long r = idx - (long)w * DDL;
    const float* src = (w == 0) ? Wq : (w == 1) ? Wk : Wv;
    f16 h, l; split2(src[r], h, l);
    ohi[idx] = h; olo[idx] = l;
}

// ================ f16 transpose (hi only): [R][C] -> [C][R] ====================
__global__ void __launch_bounds__(256)
transpose_hi(const f16* __restrict__ ihi, f16* __restrict__ ohi,
             int R, int Ccols, long sIn, long sOut)
{
    __shared__ unsigned short t[32][33];
    const int c0 = blockIdx.x * 32, r0 = blockIdx.y * 32;
    const int tx = threadIdx.x & 31, ty = threadIdx.x >> 5;
    const f16* a = ihi + sIn * blockIdx.z;
    f16* o = ohi + sOut * blockIdx.z;
#pragma unroll
    for (int j = 0; j < 32; j += 8)
        t[ty + j][tx] = __half_as_ushort(a[(long)(r0 + ty + j) * Ccols + c0 + tx]);
    __syncthreads();
#pragma unroll
    for (int j = 0; j < 32; j += 8)
        o[(long)(c0 + ty + j) * R + r0 + tx] = __ushort_as_half(t[tx][ty + j]);
}

// ============= fused head bias: b'[l][qkv][a][e] = b_qkv . Wh[l][a][:,e] + bh ==
__global__ void __launch_bounds__(256)
bias_head_kernel(const float* __restrict__ bq, const float* __restrict__ bk,
                 const float* __restrict__ bv, const float* __restrict__ bh,
                 const f16* __restrict__ wht_hi, const f16* __restrict__ wht_lo,
                 float* __restrict__ out)
{
    const int warpId = (blockIdx.x * blockDim.x + threadIdx.x) >> 5;
    const int lane = threadIdx.x & 31;
    const int total = NLAYER * 3 * NHEAD * DHEAD;
    if (warpId >= total) return;
    const int e = warpId & (DHEAD - 1);
    const int a = (warpId / DHEAD) & (NHEAD - 1);
    const int qkv = (warpId / (DHEAD * NHEAD)) % 3;
    const int l = warpId / (DHEAD * NHEAD * 3);
    const float* bsrc = ((qkv == 0) ? bq : (qkv == 1) ? bk : bv) + (long)l * DIM;
    const long wrow = (((long)l * NHEAD + a) * DHEAD + e) * DIM;
    float s = 0.0f;
    for (int i = lane; i < DIM; i += 32)
        s += bsrc[i] * (__half2float(wht_hi[wrow + i]) + __half2float(wht_lo[wrow + i]));
#pragma unroll
    for (int off = 16; off > 0; off >>= 1) s += __shfl_down_sync(0xFFFFFFFFu, s, off);
    if (lane == 0) out[warpId] = s + bh[((long)l * NHEAD + a) * DHEAD + e];
}

// ======== fused prologue misc: copy_split(hidden) ==============================
__global__ void __launch_bounds__(256)
prep_misc(const float* __restrict__ hidden, float* __restrict__ h,
          f16* __restrict__ dhi, f16* __restrict__ dlo)
{
    const int idx = blockIdx.x * blockDim.x + threadIdx.x;
    if (idx < SEQ * DIM) {
        float v = hidden[idx];
        h[idx] = v;
        f16 hh, ll; split2(v, hh, ll);
        dhi[idx] = hh; dlo[idx] = ll;
    }
}

// ============ softmax over rows (f16 hi/lo in, in-place hi/lo out) ============
__global__ void __launch_bounds__(256)
softmax_kernel(f16* __restrict__ shi, f16* __restrict__ slo)
{
    const size_t base = (size_t)blockIdx.x * SEQ;
    const int tid = threadIdx.x;

    float v[12];
    float mx = -1e30f;
#pragma unroll
    for (int i = 0; i < 12; i++) {
        const size_t o = base + tid + i * 256;
        v[i] = __half2float(shi[o]) + __half2float(slo[o]);
        mx = fmaxf(mx, v[i]);
    }
    __shared__ float red[256];
    red[tid] = mx;
    __syncthreads();
    for (int s = 128; s > 0; s >>= 1) {
        if (tid < s) red[tid] = fmaxf(red[tid], red[tid + s]);
        __syncthreads();
    }
    mx = red[0];
    __syncthreads();

    float sum = 0.0f;
#pragma unroll
    for (int i = 0; i < 12; i++) {
        v[i] = __expf(v[i] - mx);
        sum += v[i];
    }
    red[tid] = sum;
    __syncthreads();
    for (int s = 128; s > 0; s >>= 1) {
        if (tid < s) red[tid] += red[tid + s];
        __syncthreads();
    }
    const float inv = 1.0f / red[0];
#pragma unroll
    for (int i = 0; i < 12; i++) {
        float x = v[i] * inv;
        f16 h, l; split2(x, h, l);
        const size_t o = base + tid + i * 256;
        shi[o] = h;
        slo[o] = l;
    }
}

// ======================= add + layernorm (emit f32 + hi/lo) ====================
__global__ void __launch_bounds__(256)
add_ln_kernel(float* __restrict__ h, const float* __restrict__ x,
              const float* __restrict__ g, const float* __restrict__ b,
              f16* __restrict__ ohi, f16* __restrict__ olo)
{
    const long row = blockIdx.x;
    float* hp = h + row * (long)DIM;
    const float* xp = x + row * (long)DIM;
    const int tid = threadIdx.x;

    float v[4];
    float sum = 0.0f;
#pragma unroll
    for (int i = 0; i < 4; i++) {
        const int c = tid + i * 256;
        v[i] = hp[c] + xp[c];
        sum += v[i];
    }
    __shared__ float red[256];
    red[tid] = sum;
    __syncthreads();
    for (int s = 128; s > 0; s >>= 1) {
        if (tid < s) red[tid] += red[tid + s];
        __syncthreads();
    }
    const float mu = red[0] * (1.0f / DIM);
    __syncthreads();

    float vs = 0.0f;
#pragma unroll
    for (int i = 0; i < 4; i++) {
        const float d = v[i] - mu;
        vs += d * d;
    }
    red[tid] = vs;
    __syncthreads();
    for (int s = 128; s > 0; s >>= 1) {
        if (tid < s) red[tid] += red[tid + s];
        __syncthreads();
    }
    const float inv = rsqrtf(red[0] * (1.0f / DIM) + LN_EPS);
    __syncthreads();
#pragma unroll
    for (int i = 0; i < 4; i++) {
        const int c = tid + i * 256;
        float y = g[c] * (v[i] - mu) * inv + b[c];
        hp[c] = y;
        f16 hh, ll; split2(y, hh, ll);
        ohi[row * (long)DIM + c] = hh;
        olo[row * (long)DIM + c] = ll;
    }
}

// ======================= output heads =======================
__global__ void __launch_bounds__(256)
heads_kernel(const float* __restrict__ h, const float* __restrict__ Whead,
             const float* __restrict__ bhead, const int* __restrict__ nev,
             const int* __restrict__ nag, float* __restrict__ out, int total)
{
    const int warpId = (blockIdx.x * blockDim.x + threadIdx.x) >> 5;
    const int lane = threadIdx.x & 31;
    if (warpId >= total) return;
    const int NEv = *nev;
    const int NAg = *nag;
    int headIdx, token;
    if (warpId < 3 * NAg) {
        headIdx = warpId / NAg;
        token = NEv + warpId % NAg;
    } else {
        headIdx = 3;
        token = warpId - 3 * NAg;
    }
    const float* hr = h + (long)token * DIM;
    const float* w = Whead + (long)headIdx * DIM;
    float s = 0.0f;
    for (int i = lane; i < DIM; i += 32) s = fmaf(hr[i], w[i], s);
#pragma unroll
    for (int off = 16; off > 0; off >>= 1) s += __shfl_down_sync(0xFFFFFFFFu, s, off);
    if (lane == 0) out[warpId] = s + bhead[headIdx];
}

// ======================= host orchestration =======================
static void tcg(const f16* Ahi, const f16* Alo, int lda, long sAo, long sAi,
                const f16* Bhi, int ldb, long sBo, long sBi,
                const float* bias, long sBias, int nB,
                float* C, f16* Chi, f16* Clo, int ldc, long sC,
                int M, int N, int K, int batch, float alpha, int relu,
                int kSplit = 1, float* Cpart = nullptr)
{
    dim3 grid(N / 128, M / 128, batch * kSplit);
    mma_gemm<<<grid, 256, GSMEM_BYTES>>>(Ahi, Alo, lda, sAo, sAi, Bhi, ldb, sBo, sBi,
                                         bias, sBias, nB, C, Chi, Clo, ldc, sC, K, alpha, relu,
                                         kSplit, Cpart);
}

#define SYM(var, name) cudaGetSymbolAddress((void**)&var, name)

extern "C" void kernel_launch(void* const* d_in, const int* in_sizes, int n_in,
                              void* d_out, int out_size)
{
    const float* hidden = (const float*)d_in[0];
    const float* Wq = (const float*)d_in[1];
    const float* bq = (const float*)d_in[2];
    const float* Wk = (const float*)d_in[3];
    const float* bk = (const float*)d_in[4];
    const float* Wv = (const float*)d_in[5];
    const float* bv = (const float*)d_in[6];
    const float* Wh = (const float*)d_in[7];
    const float* bh = (const float*)d_in[8];
    const float* Wo = (const float*)d_in[9];
    const float* bo = (const float*)d_in[10];
    const float* g1 = (const float*)d_in[11];
    const float* b1n = (const float*)d_in[12];
    const float* g2 = (const float*)d_in[13];
    const float* b2n = (const float*)d_in[14];
    const float* Wf1 = (const float*)d_in[15];
    const float* bf1 = (const float*)d_in[16];
    const float* Wf2 = (const float*)d_in[17];
    const float* bf2 = (const float*)d_in[18];
    const float* Whead = (const float*)d_in[19];
    const float* bhead = (const float*)d_in[20];
    const int* n_events = (const int*)d_in[21];
    const int* n_agents = (const int*)d_in[22];
    (void)in_sizes; (void)n_in;

    cudaFuncSetAttribute(mma_gemm, cudaFuncAttributeMaxDynamicSharedMemorySize, GSMEM_BYTES);

    float *h, *tmp, *bprime, *spl;
    SYM(h, g_h); SYM(tmp, g_tmp); SYM(bprime, g_bprime); SYM(spl, g_split);
    f16 *h_hi, *h_lo, *qkvh_hi, *qkvh_lo;
    f16 *vht_hi, *ctx_hi, *ctx_lo, *f1_hi, *f1_lo, *at_hi, *at_lo;
    SYM(h_hi, g_h_hi); SYM(h_lo, g_h_lo);
    SYM(qkvh_hi, g_qkvh_hi); SYM(qkvh_lo, g_qkvh_lo);
    SYM(vht_hi, g_vht_hi);
    SYM(ctx_hi, g_ctx_hi); SYM(ctx_lo, g_ctx_lo);
    SYM(f1_hi, g_f1_hi); SYM(f1_lo, g_f1_lo);
    SYM(at_hi, g_at_hi); SYM(at_lo, g_at_lo);
    f16 *wsplit_hi, *wsplit_lo, *wpt_hi, *wpt_lo, *wot_hi, *wot_lo, *wht_hi, *wht_lo;
    f16 *w1t_hi, *w1t_lo, *w2t_hi, *w2t_lo;
    SYM(wsplit_hi, g_wsplit_hi); SYM(wsplit_lo, g_wsplit_lo);
    SYM(wpt_hi, g_wpt_hi); SYM(wpt_lo, g_wpt_lo);
    SYM(wot_hi, g_wot_hi); SYM(wot_lo, g_wot_lo);
    SYM(wht_hi, g_wht_hi); SYM(wht_lo, g_wht_lo);
    SYM(w1t_hi, g_w1t_hi); SYM(w1t_lo, g_w1t_lo);
    SYM(w2t_hi, g_w2t_hi); SYM(w2t_lo, g_w2t_lo);

    const long DD = (long)DIM * DIM;
    const long SD = (long)SEQ * DIM;
    const long SS = (long)SEQ * SEQ;
    const long SDh = (long)SEQ * DHEAD;
    const long WHL = (long)NHEAD * DHEAD * DIM;
    const long HD = (long)DHEAD * DIM;

    // ---- prologue ----
    transpose_split<<<dim3(DIM / 32, DIM / 32, NLAYER), 256>>>(Wo, wot_hi, wot_lo, DIM, DIM, DD, DD);
    transpose_split<<<dim3(DHEAD / 32, DIM / 32, NLAYER * NHEAD), 256>>>(
        Wh, wht_hi, wht_lo, DIM, DHEAD, HD, HD);
    transpose_split<<<dim3(2 * DIM / 32, DIM / 32, NLAYER), 256>>>(Wf1, w1t_hi, w1t_lo, DIM, 2 * DIM, 2 * DD, 2 * DD);
    transpose_split<<<dim3(DIM / 32, 2 * DIM / 32, NLAYER), 256>>>(Wf2, w2t_hi, w2t_lo, 2 * DIM, DIM, 2 * DD, 2 * DD);
    {
        const long totalW = 3 * (long)NLAYER * DD;
        split_plain_qkv<<<(int)((totalW + 255) / 256), 256>>>(Wq, Wk, Wv, wsplit_hi, wsplit_lo);
    }
    prep_misc<<<(SEQ * DIM + 255) / 256, 256>>>(hidden, h, h_hi, h_lo);
    {
        const int totalB = NLAYER * 3 * NHEAD * DHEAD;
        bias_head_kernel<<<(totalB * 32 + 255) / 256, 256>>>(bq, bk, bv, bh, wht_hi, wht_lo, bprime);
    }
    // W'^T[qkv][l][a] = wht[l][a] (DHEADxDIM) x Wq/k/v  (B = wsplit, hi only)
    for (int qkv = 0; qkv < 3; qkv++) {
        tcg(wht_hi, wht_lo, DIM, WHL, HD,
            wsplit_hi + (long)qkv * NLAYER * DD, DIM, DD, 0,
            nullptr, 0, NHEAD,
            nullptr, wpt_hi + (long)qkv * NLAYER * WHL, wpt_lo + (long)qkv * NLAYER * WHL,
            DIM, HD, DHEAD, DIM, DIM, NLAYER * NHEAD, 1.0f, 0);
    }

    const float attn_scale = 1.0f / 16.0f;

    for (int l = 0; l < NLAYER; l++) {
        // fused QKV+head projections: qkvh[qkv][a] = h @ W'[l][qkv][a] + b'
        tcg(h_hi, h_lo, DIM, 0, 0,
            wpt_hi + l * WHL, DIM, (long)NLAYER * WHL, HD,
            bprime + (long)l * 3 * NHEAD * DHEAD, DHEAD, NHEAD,
            nullptr, qkvh_hi, qkvh_lo, DHEAD, SDh, SEQ, DHEAD, DIM, 3 * NHEAD, 1.0f, 0);
        // Vh [head][t][e] -> [head][e][t], hi only (B-side of ctx GEMM)
        transpose_hi<<<dim3(DHEAD / 32, SEQ / 32, NHEAD), 256>>>(
            qkvh_hi + 2 * SD, vht_hi, SEQ, DHEAD, SDh, SDh);
        // scores = scale * Qh @ Kh^T -> hi/lo f16  (B = Kh hi)
        tcg(qkvh_hi, qkvh_lo, DHEAD, SDh, 0,
            qkvh_hi + SD, DHEAD, SDh, 0,
            nullptr, 0, 1,
            nullptr, at_hi, at_lo, SEQ, SS, SEQ, SEQ, DHEAD, NHEAD, attn_scale, 0);
        // softmax in-place on hi/lo
        softmax_kernel<<<NHEAD * SEQ, 256>>>(at_hi, at_lo);
        // ctx = attn @ Vh  (split-K=2 -> combine to hi/lo [t][a*DHEAD+e])
        tcg(at_hi, at_lo, SEQ, SS, 0,
            vht_hi, SEQ, SDh, 0,
            nullptr, 0, 1,
            nullptr, nullptr, nullptr, 0, 0, SEQ, DHEAD, SEQ, NHEAD, 1.0f, 0,
            2, spl);
        {
            const long total = (long)NHEAD * SEQ * DHEAD;
            combine2<<<(int)((total / 4 + 255) / 256), 256>>>(
                spl, SDh, total, DHEAD, nullptr,
                nullptr, ctx_hi, ctx_lo, DIM, DHEAD);
        }
        // attn_out = ctx @ Wo + bo (split-K=2 -> f32 tmp)
        tcg(ctx_hi, ctx_lo, DIM, 0, 0,
            wot_hi + l * DD, DIM, 0, 0,
            nullptr, 0, 1,
            nullptr, nullptr, nullptr, 0, 0, SEQ, DIM, DIM, 1, 1.0f, 0,
            2, spl);
        combine2<<<(int)((SD / 4 + 255) / 256), 256>>>(
            spl, SD, SD, DIM, bo + (long)l * DIM,
            tmp, nullptr, nullptr, DIM, 0);
        add_ln_kernel<<<SEQ, 256>>>(h, tmp, g1 + (long)l * DIM, b1n + (long)l * DIM, h_hi, h_lo);
        // FFN
        tcg(h_hi, h_lo, DIM, 0, 0,
            w1t_hi + l * 2 * DD, DIM, 0, 0,
            bf1 + (long)l * 2 * DIM, 0, 1,
            nullptr, f1_hi, f1_lo, 2 * DIM, 0, SEQ, 2 * DIM, DIM, 1, 1.0f, 1);
        tcg(f1_hi, f1_lo, 2 * DIM, 0, 0,
            w2t_hi + l * 2 * DD, 2 * DIM, 0, 0,
            nullptr, 0, 1,
            nullptr, nullptr, nullptr, 0, 0, SEQ, DIM, 2 * DIM, 1, 1.0f, 0,
            2, spl);
        combine2<<<(int)((SD / 4 + 255) / 256), 256>>>(
            spl, SD, SD, DIM, bf2 + (long)l * DIM,
            tmp, nullptr, nullptr, DIM, 0);
        add_ln_kernel<<<SEQ, 256>>>(h, tmp, g2 + (long)l * DIM, b2n + (long)l * DIM, h_hi, h_lo);
    }

    const int blocks = (out_size * 32 + 255) / 256;
    heads_kernel<<<blocks, 256>>>(h, Whead, bhead, n_events, n_agents, (float*)d_out, out_size);
}

// round 12
// speedup vs baseline: 2.5019x; 1.5477x over previous
#include <cuda_runtime.h>
#include <cuda_fp16.h>
#include <cstdint>
#include <math.h>

#define SEQ 3072
#define DIM 1024
#define NHEAD 4
#define DHEAD 256
#define NLAYER 4
#define LN_EPS 1e-5f
typedef __half f16;

// ======================= scratch (static device arrays) =======================
__device__ float g_h[SEQ * DIM];
__device__ float g_tmp[SEQ * DIM];
__device__ float g_split[2 * SEQ * DIM];                             // split-K partials

__device__ f16 g_h_hi[SEQ * DIM];
__device__ f16 g_qkvh[3 * SEQ * DIM];                                // [qkv][head][t][e]
__device__ f16 g_vht[SEQ * DIM];                                     // [head][e][t]
__device__ f16 g_ctx[SEQ * DIM];                                     // [t][head*DHEAD+e]
__device__ f16 g_f1[SEQ * 2 * DIM];
__device__ f16 g_at[(size_t)NHEAD * SEQ * SEQ];                      // scores/attn

// weights (fp16 hi; wht also keeps lo for the f32-exact bias fold)
__device__ f16 g_wsplit[3 * NLAYER * DIM * DIM];                     // [qkv][l][in][out]
__device__ f16 g_wpt[3 * NLAYER * NHEAD * DHEAD * DIM];              // W'^T [qkv][l][a][e][in]
__device__ f16 g_wot[NLAYER * DIM * DIM];
__device__ f16 g_wht_hi[NLAYER * NHEAD * DHEAD * DIM], g_wht_lo[NLAYER * NHEAD * DHEAD * DIM];
__device__ f16 g_w1t[NLAYER * DIM * 2 * DIM];
__device__ f16 g_w2t[NLAYER * 2 * DIM * DIM];
__device__ float g_bprime[NLAYER * 3 * NHEAD * DHEAD];               // [l][qkv][a][e]

// ======================= helpers =======================
__device__ __forceinline__ uint32_t s2u(const void* p) {
    uint32_t a;
    asm("{ .reg .u64 t; cvta.to.shared.u64 t, %1; cvt.u32.u64 %0, t; }" : "=r"(a) : "l"(p));
    return a;
}
__device__ __forceinline__ void split2(float x, f16& h, f16& l) {
    h = __float2half_rn(x);
    l = __float2half_rn(x - __half2float(h));
}
__device__ __forceinline__ void cp16(uint32_t dst, const void* src) {
    asm volatile("cp.async.cg.shared.global [%0], [%1], 16;" :: "r"(dst), "l"(src) : "memory");
}
#define CP_COMMIT() asm volatile("cp.async.commit_group;" ::: "memory")
#define CP_WAIT(n)  asm volatile("cp.async.wait_group %0;" :: "n"(n) : "memory")

__device__ __forceinline__ void ldm_x4(uint32_t* r, uint32_t addr) {
    asm volatile("ldmatrix.sync.aligned.m8n8.x4.shared.b16 {%0,%1,%2,%3}, [%4];"
                 : "=r"(r[0]), "=r"(r[1]), "=r"(r[2]), "=r"(r[3]) : "r"(addr));
}
__device__ __forceinline__ void mma_f16(float* c, const uint32_t* a, const uint32_t* b) {
    asm volatile(
        "mma.sync.aligned.m16n8k16.row.col.f32.f16.f16.f32 "
        "{%0,%1,%2,%3}, {%4,%5,%6,%7}, {%8,%9}, {%0,%1,%2,%3};"
        : "+f"(c[0]), "+f"(c[1]), "+f"(c[2]), "+f"(c[3])
        : "r"(a[0]), "r"(a[1]), "r"(a[2]), "r"(a[3]), "r"(b[0]), "r"(b[1]));
}

// ======================= fp16 mma.sync GEMM =======================
// C[m][n] = alpha * sum_k A[m][k]*B[n][k] + bias[n]   (A, B fp16; f32 accum)
// Tile 128x128, BK=64, 3-stage cp.async (32KB/stage: A 16K | B 16K), SW128, occ 1.
// Optional split-K: grid.z = batch*kSplit; partials Cpart[(zs*nzb+zb)*M*Npart + ...].
#define GSMEM_BYTES 98304
#define STAGE_BYTES 32768u

__global__ void __launch_bounds__(256, 1)
mma_gemm(const f16* __restrict__ A, int lda, long sAo, long sAi,
         const f16* __restrict__ B, int ldb, long sBo, long sBi,
         const float* __restrict__ bias, long sBias, int nB,
         float* __restrict__ C, f16* __restrict__ Chi,
         int ldc, long sC, int K, float alpha, int relu,
         int kSplit, float* __restrict__ Cpart)
{
    extern __shared__ char sm[];
    const uint32_t sb = s2u(sm);
    const int tid = threadIdx.x;
    const int wid = tid >> 5;
    const int lane = tid & 31;
    const int wm = wid >> 2;
    const int wn = wid & 3;
    int zb = blockIdx.z;
    int zs = 0;
    if (kSplit > 1) { zs = zb % kSplit; zb /= kSplit; }
    const int zo = zb / nB;
    const int zi = zb - zo * nB;
    const long row0 = (long)blockIdx.y * 128;
    const long col0 = (long)blockIdx.x * 128;

    const int Ksub = K / kSplit;
    const long koff = (long)zs * Ksub;

    A += zo * sAo + zi * sAi + koff;
    B += zo * sBo + zi * sBi + koff;

    const int nch = Ksub >> 6;

    auto load_chunk = [&](int ch, int stage) {
        const long k0 = (long)ch << 6;
#pragma unroll
        for (int i = 0; i < 8; i++) {
            const int u = tid + (i << 8);
            const int t = u >> 10;          // 0=A 1=B
            const int q = u & 1023;         // row*8 + seg
            const long r = q >> 3;
            const int sg = (q & 7) << 3;
            const f16* p = (t == 0) ? (A + (row0 + r) * lda) : (B + (col0 + r) * ldb);
            uint32_t off = (uint32_t)(q << 4);
            off ^= (off >> 3) & 0x70;
            cp16(sb + (uint32_t)stage * STAGE_BYTES + (uint32_t)t * 16384u + off, p + k0 + sg);
        }
        CP_COMMIT();
    };

    float acc[4][4][4];
#pragma unroll
    for (int a = 0; a < 4; a++)
#pragma unroll
        for (int b = 0; b < 4; b++)
#pragma unroll
            for (int c = 0; c < 4; c++) acc[a][b][c] = 0.0f;

    load_chunk(0, 0);
    load_chunk(1, 1);

    for (int ch = 0; ch < nch; ch++) {
        if (ch + 2 < nch) {
            load_chunk(ch + 2, (ch + 2) % 3);
            CP_WAIT(2);
        } else {
            CP_WAIT(0);
        }
        __syncthreads();

        const uint32_t stg = sb + (uint32_t)(ch % 3) * STAGE_BYTES;

#pragma unroll
        for (int ks = 0; ks < 4; ks++) {
            uint32_t ah[4][4], bh[2][4];
#pragma unroll
            for (int mt = 0; mt < 4; mt++) {
                const int row = wm * 64 + mt * 16 + (lane & 15);
                const int colb = ks * 32 + ((lane >> 4) << 4);
                uint32_t off = (uint32_t)(row * 128 + colb);
                off ^= (off >> 3) & 0x70;
                ldm_x4(ah[mt], stg + off);
            }
#pragma unroll
            for (int np = 0; np < 2; np++) {
                const int row = wn * 32 + np * 16 + (lane & 7) + ((lane >> 4) << 3);
                const int colb = ks * 32 + (((lane >> 3) & 1) << 4);
                uint32_t off = (uint32_t)(row * 128 + colb);
                off ^= (off >> 3) & 0x70;
                ldm_x4(bh[np], stg + 16384u + off);
            }
#pragma unroll
            for (int mt = 0; mt < 4; mt++)
#pragma unroll
                for (int nt = 0; nt < 4; nt++) {
                    const uint32_t* bhp = &bh[nt >> 1][(nt & 1) * 2];
                    mma_f16(acc[mt][nt], ah[mt], bhp);
                }
        }
        __syncthreads();
    }

    // -------- epilogue --------
    if (kSplit > 1) {
        const long Npart = (long)gridDim.x * 128;
        const long M = (long)gridDim.y * 128;
        const int nzb = gridDim.z / kSplit;
        float* dst = Cpart + ((long)zs * nzb + zb) * M * Npart;
#pragma unroll
        for (int mt = 0; mt < 4; mt++)
#pragma unroll
            for (int nt = 0; nt < 4; nt++) {
                float* d = acc[mt][nt];
                const long gm = row0 + wm * 64 + mt * 16 + (lane >> 2);
                const long gn = col0 + wn * 32 + nt * 8 + (lane & 3) * 2;
#pragma unroll
                for (int half = 0; half < 2; half++) {
                    const long r = gm + half * 8;
                    *(float2*)(dst + r * Npart + gn) =
                        make_float2(d[half * 2 + 0] * alpha, d[half * 2 + 1] * alpha);
                }
            }
        return;
    }

    float* Cz = C ? C + sC * zb : nullptr;
    f16* Hz = Chi ? Chi + sC * zb : nullptr;
    const float* bz = bias ? bias + (long)zb * sBias : nullptr;

#pragma unroll
    for (int mt = 0; mt < 4; mt++)
#pragma unroll
        for (int nt = 0; nt < 4; nt++) {
            float* d = acc[mt][nt];
            const long gm = row0 + wm * 64 + mt * 16 + (lane >> 2);
            const long gn = col0 + wn * 32 + nt * 8 + (lane & 3) * 2;
            float b0 = 0.0f, b1 = 0.0f;
            if (bz) { b0 = __ldg(bz + gn); b1 = __ldg(bz + gn + 1); }
#pragma unroll
            for (int half = 0; half < 2; half++) {
                const long r = gm + half * 8;
                float x0 = d[half * 2 + 0] * alpha + b0;
                float x1 = d[half * 2 + 1] * alpha + b1;
                if (relu) { x0 = fmaxf(x0, 0.0f); x1 = fmaxf(x1, 0.0f); }
                const long o = r * ldc + gn;
                if (Cz) *(float2*)(Cz + o) = make_float2(x0, x1);
                if (Hz) {
                    uint32_t wh = (uint32_t)__half_as_ushort(__float2half_rn(x0)) |
                                  ((uint32_t)__half_as_ushort(__float2half_rn(x1)) << 16);
                    *(uint32_t*)(Hz + o) = wh;
                }
            }
        }
}

// =============== split-K combine: out = p0 + p1 (+bias) -> f32 / f16 ==========
__global__ void __launch_bounds__(256)
combine2(const float* __restrict__ part, long perMat, long total,
         int Npart, const float* __restrict__ bias,
         float* __restrict__ outF, f16* __restrict__ outH,
         int ldc, long sC)
{
    const long i = ((long)blockIdx.x * blockDim.x + threadIdx.x) * 4;
    if (i >= total) return;
    const long zb = i / perMat;
    const long rem = i - zb * perMat;
    const long m = rem / Npart;
    const int n = (int)(rem - m * Npart);
    float4 p0 = *(const float4*)(part + i);
    float4 p1 = *(const float4*)(part + total + i);
    float x0 = p0.x + p1.x, x1 = p0.y + p1.y, x2 = p0.z + p1.z, x3 = p0.w + p1.w;
    if (bias) {
        x0 += __ldg(bias + n); x1 += __ldg(bias + n + 1);
        x2 += __ldg(bias + n + 2); x3 += __ldg(bias + n + 3);
    }
    const long o = zb * sC + m * ldc + n;
    if (outF) *(float4*)(outF + o) = make_float4(x0, x1, x2, x3);
    if (outH) {
        uint2 wh;
        wh.x = (uint32_t)__half_as_ushort(__float2half_rn(x0)) |
               ((uint32_t)__half_as_ushort(__float2half_rn(x1)) << 16);
        wh.y = (uint32_t)__half_as_ushort(__float2half_rn(x2)) |
               ((uint32_t)__half_as_ushort(__float2half_rn(x3)) << 16);
        *(uint2*)(outH + o) = wh;
    }
}

// ============= transpose f32 -> f16 (hi only): [R][C] -> [C][R] ================
__global__ void __launch_bounds__(256)
transpose_f32_f16(const float* __restrict__ in, f16* __restrict__ ohi,
                  int R, int Ccols, long sIn, long sOut)
{
    __shared__ float t[32][33];
    const float* ip = in + sIn * blockIdx.z;
    const int c0 = blockIdx.x * 32, r0 = blockIdx.y * 32;
    const int tx = threadIdx.x & 31, ty = threadIdx.x >> 5;
#pragma unroll
    for (int j = 0; j < 32; j += 8)
        t[ty + j][tx] = ip[(long)(r0 + ty + j) * Ccols + c0 + tx];
    __syncthreads();
#pragma unroll
    for (int j = 0; j < 32; j += 8) {
        long o = sOut * blockIdx.z + (long)(c0 + ty + j) * R + r0 + tx;
        ohi[o] = __float2half_rn(t[tx][ty + j]);
    }
}

// ============= transpose f32 -> f16 hi/lo: [R][C] -> [C][R] (for Wh) ===========
__global__ void __launch_bounds__(256)
transpose_split(const float* __restrict__ in, f16* __restrict__ ohi, f16* __restrict__ olo,
                int R, int Ccols, long sIn, long sOut)
{
    __shared__ float t[32][33];
    const float* ip = in + sIn * blockIdx.z;
    const int c0 = blockIdx.x * 32, r0 = blockIdx.y * 32;
    const int tx = threadIdx.x & 31, ty = threadIdx.x >> 5;
#pragma unroll
    for (int j = 0; j < 32; j += 8)
        t[ty + j][tx] = ip[(long)(r0 + ty + j) * Ccols + c0 + tx];
    __syncthreads();
#pragma unroll
    for (int j = 0; j < 32; j += 8) {
        float x = t[tx][ty + j];
        f16 h, l; split2(x, h, l);
        long o = sOut * blockIdx.z + (long)(c0 + ty + j) * R + r0 + tx;
        ohi[o] = h; olo[o] = l;
    }
}

// ========== plain f16 cast of Wq|Wk|Wv into [qkv][l][in][out] =================
__global__ void __launch_bounds__(256)
split_plain_qkv(const float* __restrict__ Wq, const float* __restrict__ Wk,
                const float* __restrict__ Wv, f16* __restrict__ ohi)
{
    const long DDL = (long)NLAYER * DIM * DIM;
    const long idx = (long)blockIdx.x * blockDim.x + threadIdx.x;
    if (idx >= 3 * DDL) return;
    const int w = (int)(idx / DDL);
    const long r = idx - (long)w * DDL;
    const float* src = (w == 0) ? Wq : (w == 1) ? Wk : Wv;
    ohi[idx] = __float2half_rn(src[r]);
}

// ================ f16 transpose: [R][C] -> [C][R] ==============================
__global__ void __launch_bounds__(256)
transpose_hi(const f16* __restrict__ ihi, f16* __restrict__ ohi,
             int R, int Ccols, long sIn, long sOut)
{
    __shared__ unsigned short t[32][33];
    const int c0 = blockIdx.x * 32, r0 = blockIdx.y * 32;
    const int tx = threadIdx.x & 31, ty = threadIdx.x >> 5;
    const f16* a = ihi + sIn * blockIdx.z;
    f16* o = ohi + sOut * blockIdx.z;
#pragma unroll
    for (int j = 0; j < 32; j += 8)
        t[ty + j][tx] = __half_as_ushort(a[(long)(r0 + ty + j) * Ccols + c0 + tx]);
    __syncthreads();
#pragma unroll
    for (int j = 0; j < 32; j += 8)
        o[(long)(c0 + ty + j) * R + r0 + tx] = __ushort_as_half(t[tx][ty + j]);
}

// ============= fused head bias: b'[l][qkv][a][e] = b_qkv . Wh[l][a][:,e] + bh ==
__global__ void __launch_bounds__(256)
bias_head_kernel(const float* __restrict__ bq, const float* __restrict__ bk,
                 const float* __restrict__ bv, const float* __restrict__ bh,
                 const f16* __restrict__ wht_hi, const f16* __restrict__ wht_lo,
                 float* __restrict__ out)
{
    const int warpId = (blockIdx.x * blockDim.x + threadIdx.x) >> 5;
    const int lane = threadIdx.x & 31;
    const int total = NLAYER * 3 * NHEAD * DHEAD;
    if (warpId >= total) return;
    const int e = warpId & (DHEAD - 1);
    const int a = (warpId / DHEAD) & (NHEAD - 1);
    const int qkv = (warpId / (DHEAD * NHEAD)) % 3;
    const int l = warpId / (DHEAD * NHEAD * 3);
    const float* bsrc = ((qkv == 0) ? bq : (qkv == 1) ? bk : bv) + (long)l * DIM;
    const long wrow = (((long)l * NHEAD + a) * DHEAD + e) * DIM;
    float s = 0.0f;
    for (int i = lane; i < DIM; i += 32)
        s += bsrc[i] * (__half2float(wht_hi[wrow + i]) + __half2float(wht_lo[wrow + i]));
#pragma unroll
    for (int off = 16; off > 0; off >>= 1) s += __shfl_down_sync(0xFFFFFFFFu, s, off);
    if (lane == 0) out[warpId] = s + bh[((long)l * NHEAD + a) * DHEAD + e];
}

// ======== fused prologue misc: copy + f16 cast of hidden =======================
__global__ void __launch_bounds__(256)
prep_misc(const float* __restrict__ hidden, float* __restrict__ h,
          f16* __restrict__ dhi)
{
    const int idx = blockIdx.x * blockDim.x + threadIdx.x;
    if (idx < SEQ * DIM) {
        float v = hidden[idx];
        h[idx] = v;
        dhi[idx] = __float2half_rn(v);
    }
}

// ============ softmax over rows (f16 in, in-place f16 out) =====================
__global__ void __launch_bounds__(256)
softmax_kernel(f16* __restrict__ s16)
{
    const size_t base = (size_t)blockIdx.x * SEQ;
    const int tid = threadIdx.x;

    float v[12];
    float mx = -1e30f;
#pragma unroll
    for (int i = 0; i < 12; i++) {
        v[i] = __half2float(s16[base + tid + i * 256]);
        mx = fmaxf(mx, v[i]);
    }
    __shared__ float red[256];
    red[tid] = mx;
    __syncthreads();
    for (int s = 128; s > 0; s >>= 1) {
        if (tid < s) red[tid] = fmaxf(red[tid], red[tid + s]);
        __syncthreads();
    }
    mx = red[0];
    __syncthreads();

    float sum = 0.0f;
#pragma unroll
    for (int i = 0; i < 12; i++) {
        v[i] = __expf(v[i] - mx);
        sum += v[i];
    }
    red[tid] = sum;
    __syncthreads();
    for (int s = 128; s > 0; s >>= 1) {
        if (tid < s) red[tid] += red[tid + s];
        __syncthreads();
    }
    const float inv = 1.0f / red[0];
#pragma unroll
    for (int i = 0; i < 12; i++)
        s16[base + tid + i * 256] = __float2half_rn(v[i] * inv);
}

// ======================= add + layernorm (emit f32 + f16) ======================
__global__ void __launch_bounds__(256)
add_ln_kernel(float* __restrict__ h, const float* __restrict__ x,
              const float* __restrict__ g, const float* __restrict__ b,
              f16* __restrict__ ohi)
{
    const long row = blockIdx.x;
    float* hp = h + row * (long)DIM;
    const float* xp = x + row * (long)DIM;
    const int tid = threadIdx.x;

    float v[4];
    float sum = 0.0f;
#pragma unroll
    for (int i = 0; i < 4; i++) {
        const int c = tid + i * 256;
        v[i] = hp[c] + xp[c];
        sum += v[i];
    }
    __shared__ float red[256];
    red[tid] = sum;
    __syncthreads();
    for (int s = 128; s > 0; s >>= 1) {
        if (tid < s) red[tid] += red[tid + s];
        __syncthreads();
    }
    const float mu = red[0] * (1.0f / DIM);
    __syncthreads();

    float vs = 0.0f;
#pragma unroll
    for (int i = 0; i < 4; i++) {
        const float d = v[i] - mu;
        vs += d * d;
    }
    red[tid] = vs;
    __syncthreads();
    for (int s = 128; s > 0; s >>= 1) {
        if (tid < s) red[tid] += red[tid + s];
        __syncthreads();
    }
    const float inv = rsqrtf(red[0] * (1.0f / DIM) + LN_EPS);
    __syncthreads();
#pragma unroll
    for (int i = 0; i < 4; i++) {
        const int c = tid + i * 256;
        float y = g[c] * (v[i] - mu) * inv + b[c];
        hp[c] = y;
        ohi[row * (long)DIM + c] = __float2half_rn(y);
    }
}

// ======================= output heads =======================
__global__ void __launch_bounds__(256)
heads_kernel(const float* __restrict__ h, const float* __restrict__ Whead,
             const float* __restrict__ bhead, const int* __restrict__ nev,
             const int* __restrict__ nag, float* __restrict__ out, int total)
{
    const int warpId = (blockIdx.x * blockDim.x + threadIdx.x) >> 5;
    const int lane = threadIdx.x & 31;
    if (warpId >= total) return;
    const int NEv = *nev;
    const int NAg = *nag;
    int headIdx, token;
    if (warpId < 3 * NAg) {
        headIdx = warpId / NAg;
        token = NEv + warpId % NAg;
    } else {
        headIdx = 3;
        token = warpId - 3 * NAg;
    }
    const float* hr = h + (long)token * DIM;
    const float* w = Whead + (long)headIdx * DIM;
    float s = 0.0f;
    for (int i = lane; i < DIM; i += 32) s = fmaf(hr[i], w[i], s);
#pragma unroll
    for (int off = 16; off > 0; off >>= 1) s += __shfl_down_sync(0xFFFFFFFFu, s, off);
    if (lane == 0) out[warpId] = s + bhead[headIdx];
}

// ======================= host orchestration =======================
static void tcg(const f16* A, int lda, long sAo, long sAi,
                const f16* B, int ldb, long sBo, long sBi,
                const float* bias, long sBias, int nB,
                float* C, f16* Chi, int ldc, long sC,
                int M, int N, int K, int batch, float alpha, int relu,
                int kSplit = 1, float* Cpart = nullptr)
{
    dim3 grid(N / 128, M / 128, batch * kSplit);
    mma_gemm<<<grid, 256, GSMEM_BYTES>>>(A, lda, sAo, sAi, B, ldb, sBo, sBi,
                                         bias, sBias, nB, C, Chi, ldc, sC, K, alpha, relu,
                                         kSplit, Cpart);
}

#define SYM(var, name) cudaGetSymbolAddress((void**)&var, name)

extern "C" void kernel_launch(void* const* d_in, const int* in_sizes, int n_in,
                              void* d_out, int out_size)
{
    const float* hidden = (const float*)d_in[0];
    const float* Wq = (const float*)d_in[1];
    const float* bq = (const float*)d_in[2];
    const float* Wk = (const float*)d_in[3];
    const float* bk = (const float*)d_in[4];
    const float* Wv = (const float*)d_in[5];
    const float* bv = (const float*)d_in[6];
    const float* Wh = (const float*)d_in[7];
    const float* bh = (const float*)d_in[8];
    const float* Wo = (const float*)d_in[9];
    const float* bo = (const float*)d_in[10];
    const float* g1 = (const float*)d_in[11];
    const float* b1n = (const float*)d_in[12];
    const float* g2 = (const float*)d_in[13];
    const float* b2n = (const float*)d_in[14];
    const float* Wf1 = (const float*)d_in[15];
    const float* bf1 = (const float*)d_in[16];
    const float* Wf2 = (const float*)d_in[17];
    const float* bf2 = (const float*)d_in[18];
    const float* Whead = (const float*)d_in[19];
    const float* bhead = (const float*)d_in[20];
    const int* n_events = (const int*)d_in[21];
    const int* n_agents = (const int*)d_in[22];
    (void)in_sizes; (void)n_in;

    cudaFuncSetAttribute(mma_gemm, cudaFuncAttributeMaxDynamicSharedMemorySize, GSMEM_BYTES);

    float *h, *tmp, *bprime, *spl;
    SYM(h, g_h); SYM(tmp, g_tmp); SYM(bprime, g_bprime); SYM(spl, g_split);
    f16 *h_hi, *qkvh, *vht, *ctx, *f1, *at;
    SYM(h_hi, g_h_hi); SYM(qkvh, g_qkvh); SYM(vht, g_vht);
    SYM(ctx, g_ctx); SYM(f1, g_f1); SYM(at, g_at);
    f16 *wsplit, *wpt, *wot, *wht_hi, *wht_lo, *w1t, *w2t;
    SYM(wsplit, g_wsplit); SYM(wpt, g_wpt); SYM(wot, g_wot);
    SYM(wht_hi, g_wht_hi); SYM(wht_lo, g_wht_lo);
    SYM(w1t, g_w1t); SYM(w2t, g_w2t);

    const long DD = (long)DIM * DIM;
    const long SD = (long)SEQ * DIM;
    const long SS = (long)SEQ * SEQ;
    const long SDh = (long)SEQ * DHEAD;
    const long WHL = (long)NHEAD * DHEAD * DIM;
    const long HD = (long)DHEAD * DIM;

    // ---- prologue ----
    transpose_f32_f16<<<dim3(DIM / 32, DIM / 32, NLAYER), 256>>>(Wo, wot, DIM, DIM, DD, DD);
    transpose_split<<<dim3(DHEAD / 32, DIM / 32, NLAYER * NHEAD), 256>>>(
        Wh, wht_hi, wht_lo, DIM, DHEAD, HD, HD);
    transpose_f32_f16<<<dim3(2 * DIM / 32, DIM / 32, NLAYER), 256>>>(Wf1, w1t, DIM, 2 * DIM, 2 * DD, 2 * DD);
    transpose_f32_f16<<<dim3(DIM / 32, 2 * DIM / 32, NLAYER), 256>>>(Wf2, w2t, 2 * DIM, DIM, 2 * DD, 2 * DD);
    {
        const long totalW = 3 * (long)NLAYER * DD;
        split_plain_qkv<<<(int)((totalW + 255) / 256), 256>>>(Wq, Wk, Wv, wsplit);
    }
    prep_misc<<<(SEQ * DIM + 255) / 256, 256>>>(hidden, h, h_hi);
    {
        const int totalB = NLAYER * 3 * NHEAD * DHEAD;
        bias_head_kernel<<<(totalB * 32 + 255) / 256, 256>>>(bq, bk, bv, bh, wht_hi, wht_lo, bprime);
    }
    // W'^T[qkv][l][a] = wht[l][a] (DHEADxDIM) x Wq/k/v
    for (int qkv = 0; qkv < 3; qkv++) {
        tcg(wht_hi, DIM, WHL, HD,
            wsplit + (long)qkv * NLAYER * DD, DIM, DD, 0,
            nullptr, 0, NHEAD,
            nullptr, wpt + (long)qkv * NLAYER * WHL,
            DIM, HD, DHEAD, DIM, DIM, NLAYER * NHEAD, 1.0f, 0);
    }

    const float attn_scale = 1.0f / 16.0f;

    for (int l = 0; l < NLAYER; l++) {
        // fused QKV+head projections: qkvh[qkv][a] = h @ W'[l][qkv][a] + b'
        tcg(h_hi, DIM, 0, 0,
            wpt + l * WHL, DIM, (long)NLAYER * WHL, HD,
            bprime + (long)l * 3 * NHEAD * DHEAD, DHEAD, NHEAD,
            nullptr, qkvh, DHEAD, SDh, SEQ, DHEAD, DIM, 3 * NHEAD, 1.0f, 0);
        // Vh [head][t][e] -> [head][e][t]
        transpose_hi<<<dim3(DHEAD / 32, SEQ / 32, NHEAD), 256>>>(
            qkvh + 2 * SD, vht, SEQ, DHEAD, SDh, SDh);
        // scores = scale * Qh @ Kh^T -> f16
        tcg(qkvh, DHEAD, SDh, 0,
            qkvh + SD, DHEAD, SDh, 0,
            nullptr, 0, 1,
            nullptr, at, SEQ, SS, SEQ, SEQ, DHEAD, NHEAD, attn_scale, 0);
        // softmax in-place
        softmax_kernel<<<NHEAD * SEQ, 256>>>(at);
        // ctx = attn @ Vh  (split-K=2 -> combine to f16 [t][a*DHEAD+e])
        tcg(at, SEQ, SS, 0,
            vht, SEQ, SDh, 0,
            nullptr, 0, 1,
            nullptr, nullptr, 0, 0, SEQ, DHEAD, SEQ, NHEAD, 1.0f, 0,
            2, spl);
        {
            const long total = (long)NHEAD * SEQ * DHEAD;
            combine2<<<(int)((total / 4 + 255) / 256), 256>>>(
                spl, SDh, total, DHEAD, nullptr,
                nullptr, ctx, DIM, DHEAD);
        }
        // attn_out = ctx @ Wo + bo (split-K=2 -> f32 tmp)
        tcg(ctx, DIM, 0, 0,
            wot + l * DD, DIM, 0, 0,
            nullptr, 0, 1,
            nullptr, nullptr, 0, 0, SEQ, DIM, DIM, 1, 1.0f, 0,
            2, spl);
        combine2<<<(int)((SD / 4 + 255) / 256), 256>>>(
            spl, SD, SD, DIM, bo + (long)l * DIM,
            tmp, nullptr, DIM, 0);
        add_ln_kernel<<<SEQ, 256>>>(h, tmp, g1 + (long)l * DIM, b1n + (long)l * DIM, h_hi);
        // FFN
        tcg(h_hi, DIM, 0, 0,
            w1t + l * 2 * DD, DIM, 0, 0,
            bf1 + (long)l * 2 * DIM, 0, 1,
            nullptr, f1, 2 * DIM, 0, SEQ, 2 * DIM, DIM, 1, 1.0f, 1);
        tcg(f1, 2 * DIM, 0, 0,
            w2t + l * 2 * DD, 2 * DIM, 0, 0,
            nullptr, 0, 1,
            nullptr, nullptr, 0, 0, SEQ, DIM, 2 * DIM, 1, 1.0f, 0,
            2, spl);
        combine2<<<(int)((SD / 4 + 255) / 256), 256>>>(
            spl, SD, SD, DIM, bf2 + (long)l * DIM,
            tmp, nullptr, DIM, 0);
        add_ln_kernel<<<SEQ, 256>>>(h, tmp, g2 + (long)l * DIM, b2n + (long)l * DIM, h_hi);
    }

    const int blocks = (out_size * 32 + 255) / 256;
    heads_kernel<<<blocks, 256>>>(h, Whead, bhead, n_events, n_agents, (float*)d_out, out_size);
}